// round 5
// baseline (speedup 1.0000x reference)
#include <cuda_runtime.h>

#define BATCH 96
#define SEQ   320
#define DIM   256
#define HEADS 8
#define DHEAD 32
#define NROWS (BATCH*SEQ)   /* 30720 */

// ---------------- scratch (device globals: no allocation allowed) ----------
__device__ float g_xn[NROWS*DIM];
__device__ float g_q [NROWS*DIM];   // (B*N, 256) cols packed h*32+dh
__device__ float g_k [NROWS*DIM];
__device__ float g_v [NROWS*DIM];
__device__ float g_o [NROWS*DIM];   // attention output, (B*N, 256)

// xs row (Bi, n)  ->  offset into the 7D x tensor (elems = innermost size)
__device__ __forceinline__ size_t x_offset(int Bi, int n, int elems)
{
    int b  = Bi / 48, xy = Bi % 48;
    int gx = xy >> 3, gy = xy & 7;
    int l  = n >> 6,  r  = n & 63;
    int w1 = r >> 3,  w2 = r & 7;
    return ((((((size_t)b*5 + l)*6 + gx)*8 + gy)*8 + w1)*8 + w2) * (size_t)elems;
}

// ---------------- kernel 1: gather-transpose + LayerNorm --------------------
__global__ __launch_bounds__(256)
void ln_kernel(const float* __restrict__ x,
               const float* __restrict__ gamma,
               const float* __restrict__ beta)
{
    int row = blockIdx.x;                 // 0..30719 = Bi*320 + n
    int Bi  = row / SEQ;
    int n   = row % SEQ;
    size_t xoff = x_offset(Bi, n, DIM);

    int d = threadIdx.x;                  // 0..255
    float v = x[xoff + d];

    float s1 = v, s2 = v * v;
    #pragma unroll
    for (int off = 16; off > 0; off >>= 1) {
        s1 += __shfl_xor_sync(0xffffffff, s1, off);
        s2 += __shfl_xor_sync(0xffffffff, s2, off);
    }
    __shared__ float sh1[8], sh2[8];
    int wid = d >> 5, lid = d & 31;
    if (lid == 0) { sh1[wid] = s1; sh2[wid] = s2; }
    __syncthreads();
    if (wid == 0) {
        float a  = (lid < 8) ? sh1[lid] : 0.f;
        float b2 = (lid < 8) ? sh2[lid] : 0.f;
        #pragma unroll
        for (int off = 4; off > 0; off >>= 1) {
            a  += __shfl_xor_sync(0xffffffff, a,  off);
            b2 += __shfl_xor_sync(0xffffffff, b2, off);
        }
        if (lid == 0) { sh1[0] = a; sh2[0] = b2; }
    }
    __syncthreads();
    float mu  = sh1[0] * (1.0f / DIM);
    float var = sh2[0] * (1.0f / DIM) - mu * mu;
    float rs  = rsqrtf(var + 1e-5f);
    g_xn[(size_t)row * DIM + d] = (v - mu) * rs * gamma[d] + beta[d];
}

// ---------------- kernel 2: QKV projection (SGEMM 128x128x16) ---------------
// C(30720 x 768) = g_xn(30720 x 256) @ [w_q | w_kv](256 x 768)
// grid.y: 0,1 -> w_q cols ;  2..5 -> w_kv cols (k for <256, v for >=256)
__global__ __launch_bounds__(256)
void qkv_gemm(const float* __restrict__ Wq,
              const float* __restrict__ Wkv)
{
    __shared__ __align__(16) float As[16][128];   // [k][m]
    __shared__ __align__(16) float Bs[16][128];   // [k][n]

    int tid = threadIdx.x;
    int bx  = blockIdx.x;                 // 0..239
    int by  = blockIdx.y;                 // 0..5

    const float* Bsrc; int ldb, colbase;
    if (by < 2) { Bsrc = Wq;  ldb = 256; colbase = by * 128; }
    else        { Bsrc = Wkv; ldb = 512; colbase = (by - 2) * 128; }

    int row0 = bx * 128;
    int tx = tid & 15, ty = tid >> 4;

    float acc[8][8];
    #pragma unroll
    for (int i = 0; i < 8; i++)
        #pragma unroll
        for (int j = 0; j < 8; j++) acc[i][j] = 0.f;

    for (int k0 = 0; k0 < 256; k0 += 16) {
        #pragma unroll
        for (int p = 0; p < 2; p++) {           // A tile 128x16
            int fid = tid + p * 256;
            int ar  = fid >> 2;
            int ac  = (fid & 3) << 2;
            float4 t = *(const float4*)(g_xn + (size_t)(row0 + ar) * 256 + k0 + ac);
            As[ac + 0][ar] = t.x;
            As[ac + 1][ar] = t.y;
            As[ac + 2][ar] = t.z;
            As[ac + 3][ar] = t.w;
        }
        #pragma unroll
        for (int p = 0; p < 2; p++) {           // B tile 16x128
            int fid = tid + p * 256;
            int br  = fid >> 5;
            int bc  = (fid & 31) << 2;
            *(float4*)&Bs[br][bc] =
                *(const float4*)(Bsrc + (size_t)(k0 + br) * ldb + colbase + bc);
        }
        __syncthreads();
        #pragma unroll
        for (int kk = 0; kk < 16; kk++) {
            float ra[8], rb[8];
            *(float4*)&ra[0] = *(float4*)&As[kk][ty * 8];
            *(float4*)&ra[4] = *(float4*)&As[kk][ty * 8 + 4];
            *(float4*)&rb[0] = *(float4*)&Bs[kk][tx * 8];
            *(float4*)&rb[4] = *(float4*)&Bs[kk][tx * 8 + 4];
            #pragma unroll
            for (int i = 0; i < 8; i++)
                #pragma unroll
                for (int j = 0; j < 8; j++)
                    acc[i][j] = fmaf(ra[i], rb[j], acc[i][j]);
        }
        __syncthreads();
    }

    // epilogue: scatter into q / k / v (all stored (row, 256) packed h*32+dh)
    #pragma unroll
    for (int i = 0; i < 8; i++) {
        size_t grow = (size_t)(row0 + ty * 8 + i);
        #pragma unroll
        for (int j4 = 0; j4 < 2; j4++) {
            int jloc = colbase + tx * 8 + j4 * 4;
            float* dst;
            int col;
            if (by < 2)            { dst = g_q; col = jloc; }
            else if (jloc < 256)   { dst = g_k; col = jloc; }
            else                   { dst = g_v; col = jloc - 256; }
            float4 t = make_float4(acc[i][j4*4+0], acc[i][j4*4+1],
                                   acc[i][j4*4+2], acc[i][j4*4+3]);
            *(float4*)(dst + grow * 256 + col) = t;
        }
    }
}

// ---------------- kernel 3: attention (online softmax, 64q x 64m tiles) -----
// grid = (5 n-tiles, 8 heads, 96 batches), 256 threads (16x16)
// thread owns: S 4rows x 4cols, O 4rows x 2cols
__global__ __launch_bounds__(256)
void attn_kernel(const float* __restrict__ ctx)
{
    int nt = blockIdx.x;
    int h  = blockIdx.y;
    int Bi = blockIdx.z;
    int n0 = nt * 64;

    const float* qh = g_q + (size_t)Bi * SEQ * 256 + h * 32;
    const float* kh = g_k + (size_t)Bi * SEQ * 256 + h * 32;
    const float* vh = g_v + (size_t)Bi * SEQ * 256 + h * 32;
    const float* ctxb = ctx + (size_t)Bi * SEQ * (HEADS * SEQ) + h * SEQ;

    __shared__ __align__(16) float qt[32][68];   // [d][qrow]
    __shared__ __align__(16) float kt[32][68];   // [d][kcol]
    __shared__ __align__(16) float vs[64][36];   // [krow][d]
    __shared__ __align__(16) float ps[64][68];   // P tile

    int tid = threadIdx.x;
    int tx = tid & 15, ty = tid >> 4;
    int r0 = ty * 4;      // query rows owned
    int c0 = tx * 4;      // S columns owned
    int co = tx * 2;      // O columns owned

    // q tile (transposed into smem)
    for (int i = tid; i < 512; i += 256) {
        int r = i >> 3, d4 = (i & 7) << 2;
        float4 t = *(const float4*)(qh + (size_t)(n0 + r) * 256 + d4);
        qt[d4 + 0][r] = t.x; qt[d4 + 1][r] = t.y;
        qt[d4 + 2][r] = t.z; qt[d4 + 3][r] = t.w;
    }

    float acc[4][2];
    #pragma unroll
    for (int i = 0; i < 4; i++) { acc[i][0] = 0.f; acc[i][1] = 0.f; }
    float m_run[4] = {-1e30f, -1e30f, -1e30f, -1e30f};
    float l_run[4] = {0.f, 0.f, 0.f, 0.f};

    for (int m0 = 0; m0 < SEQ; m0 += 64) {
        __syncthreads();                          // previous tile fully consumed
        for (int i = tid; i < 512; i += 256) {    // k (transposed) + v tiles
            int r = i >> 3, d4 = (i & 7) << 2;
            float4 t = *(const float4*)(kh + (size_t)(m0 + r) * 256 + d4);
            kt[d4 + 0][r] = t.x; kt[d4 + 1][r] = t.y;
            kt[d4 + 2][r] = t.z; kt[d4 + 3][r] = t.w;
            float4 u = *(const float4*)(vh + (size_t)(m0 + r) * 256 + d4);
            vs[r][d4 + 0] = u.x; vs[r][d4 + 1] = u.y;
            vs[r][d4 + 2] = u.z; vs[r][d4 + 3] = u.w;
        }
        __syncthreads();

        // S = bias ; S += q k^T
        float S[4][4];
        #pragma unroll
        for (int rr = 0; rr < 4; rr++) {
            float4 bb = *(const float4*)(ctxb + (size_t)(n0 + r0 + rr) * (HEADS * SEQ)
                                               + m0 + c0);
            S[rr][0] = bb.x; S[rr][1] = bb.y; S[rr][2] = bb.z; S[rr][3] = bb.w;
        }
        #pragma unroll
        for (int d = 0; d < 32; d++) {
            float4 a = *(const float4*)&qt[d][r0];
            float4 b = *(const float4*)&kt[d][c0];
            float av[4] = {a.x, a.y, a.z, a.w};
            float bv[4] = {b.x, b.y, b.z, b.w};
            #pragma unroll
            for (int rr = 0; rr < 4; rr++)
                #pragma unroll
                for (int cc = 0; cc < 4; cc++)
                    S[rr][cc] = fmaf(av[rr], bv[cc], S[rr][cc]);
        }

        // online softmax (row stats reduced over the 16 tx lanes)
        #pragma unroll
        for (int rr = 0; rr < 4; rr++) {
            float m = fmaxf(fmaxf(S[rr][0], S[rr][1]), fmaxf(S[rr][2], S[rr][3]));
            #pragma unroll
            for (int off = 8; off > 0; off >>= 1)
                m = fmaxf(m, __shfl_xor_sync(0xffffffff, m, off));
            float mn   = fmaxf(m_run[rr], m);
            float corr = __expf(m_run[rr] - mn);
            float p0 = __expf(S[rr][0] - mn);
            float p1 = __expf(S[rr][1] - mn);
            float p2 = __expf(S[rr][2] - mn);
            float p3 = __expf(S[rr][3] - mn);
            float ls = p0 + p1 + p2 + p3;
            #pragma unroll
            for (int off = 8; off > 0; off >>= 1)
                ls += __shfl_xor_sync(0xffffffff, ls, off);
            l_run[rr] = l_run[rr] * corr + ls;
            m_run[rr] = mn;
            acc[rr][0] *= corr;
            acc[rr][1] *= corr;
            *(float4*)&ps[r0 + rr][c0] = make_float4(p0, p1, p2, p3);
        }
        __syncwarp();     // P rows are produced+consumed within one warp half

        // O += P @ V
        #pragma unroll 4
        for (int j = 0; j < 64; j += 4) {
            float4 rp[4];
            #pragma unroll
            for (int rr = 0; rr < 4; rr++)
                rp[rr] = *(const float4*)&ps[r0 + rr][j];
            float p_[4][4];
            #pragma unroll
            for (int rr = 0; rr < 4; rr++) {
                p_[rr][0] = rp[rr].x; p_[rr][1] = rp[rr].y;
                p_[rr][2] = rp[rr].z; p_[rr][3] = rp[rr].w;
            }
            #pragma unroll
            for (int jj = 0; jj < 4; jj++) {
                float v0 = vs[j + jj][co];
                float v1 = vs[j + jj][co + 1];
                #pragma unroll
                for (int rr = 0; rr < 4; rr++) {
                    acc[rr][0] = fmaf(p_[rr][jj], v0, acc[rr][0]);
                    acc[rr][1] = fmaf(p_[rr][jj], v1, acc[rr][1]);
                }
            }
        }
    }

    // normalize + write
    #pragma unroll
    for (int rr = 0; rr < 4; rr++) {
        float inv = 1.0f / l_run[rr];
        float2 t = make_float2(acc[rr][0] * inv, acc[rr][1] * inv);
        *(float2*)(g_o + (size_t)(Bi * SEQ + n0 + r0 + rr) * 256 + h * 32 + co) = t;
    }
}

// ---------------- kernel 4: output projection + scatter ---------------------
// out(30720 x 32) = g_o(30720 x 256) @ w_out(256 x 32), scattered to 7D layout
__global__ __launch_bounds__(256)
void outproj_kernel(const float* __restrict__ wout, float* __restrict__ out)
{
    __shared__ __align__(16) float ws[DIM * DHEAD];   // 8192 floats
    int tid = threadIdx.x;
    for (int i = tid * 4; i < DIM * DHEAD; i += 256 * 4)
        *(float4*)&ws[i] = *(const float4*)&wout[i];
    __syncthreads();

    int tg = tid >> 3;                   // 0..31  row group of 4
    int cg = tid & 7;                    // 0..7   col group of 4
    int row0 = blockIdx.x * 128 + tg * 4;

    float acc[4][4];
    #pragma unroll
    for (int i = 0; i < 4; i++)
        #pragma unroll
        for (int j = 0; j < 4; j++) acc[i][j] = 0.f;

    for (int k4 = 0; k4 < DIM; k4 += 4) {
        float ar[4][4];
        #pragma unroll
        for (int i = 0; i < 4; i++) {
            float4 t = *(const float4*)&g_o[(size_t)(row0 + i) * DIM + k4];
            ar[i][0] = t.x; ar[i][1] = t.y; ar[i][2] = t.z; ar[i][3] = t.w;
        }
        #pragma unroll
        for (int kk = 0; kk < 4; kk++) {
            float4 w = *(const float4*)&ws[(k4 + kk) * DHEAD + cg * 4];
            float wv[4] = {w.x, w.y, w.z, w.w};
            #pragma unroll
            for (int i = 0; i < 4; i++)
                #pragma unroll
                for (int j = 0; j < 4; j++)
                    acc[i][j] = fmaf(ar[i][kk], wv[j], acc[i][j]);
        }
    }

    #pragma unroll
    for (int i = 0; i < 4; i++) {
        int grow = row0 + i;
        int Bi = grow / SEQ, n = grow % SEQ;
        size_t off = x_offset(Bi, n, DHEAD) + cg * 4;
        *(float4*)(out + off) = make_float4(acc[i][0], acc[i][1], acc[i][2], acc[i][3]);
    }
}

// ---------------- launch ----------------------------------------------------
extern "C" void kernel_launch(void* const* d_in, const int* in_sizes, int n_in,
                              void* d_out, int out_size)
{
    (void)out_size;
    // expected order: x, context, w_q, w_kv, w_out, ln_g, ln_b
    int ix = 0, ictx = 1, iwq = 2, iwkv = 3, iwout = 4, ig = 5, ib = 6;
    // defensive remap by element count (ln_g/ln_b keep declaration order)
    int g_seen = -1;
    for (int i = 0; i < n_in; i++) {
        switch (in_sizes[i]) {
            case 7864320:  ix = i;    break;
            case 78643200: ictx = i;  break;
            case 65536:    iwq = i;   break;
            case 131072:   iwkv = i;  break;
            case 8192:     iwout = i; break;
            case 256:
                if (g_seen < 0) { ig = i; g_seen = i; } else { ib = i; }
                break;
            default: break;
        }
    }

    const float* x    = (const float*)d_in[ix];
    const float* ctx  = (const float*)d_in[ictx];
    const float* wq   = (const float*)d_in[iwq];
    const float* wkv  = (const float*)d_in[iwkv];
    const float* wout = (const float*)d_in[iwout];
    const float* lng  = (const float*)d_in[ig];
    const float* lnb  = (const float*)d_in[ib];
    float* out = (float*)d_out;

    ln_kernel<<<NROWS, 256>>>(x, lng, lnb);

    dim3 g2(240, 6);
    qkv_gemm<<<g2, 256>>>(wq, wkv);

    dim3 g3(5, HEADS, BATCH);
    attn_kernel<<<g3, 256>>>(ctx);

    outproj_kernel<<<240, 256>>>(wout, out);
}

// round 7
// speedup vs baseline: 1.5718x; 1.5718x over previous
#include <cuda_runtime.h>
#include <cuda_bf16.h>
#include <cstdint>

#define BATCH 96
#define SEQ   320
#define DIM   256
#define HEADS 8
#define DHEAD 32
#define NROWS (BATCH*SEQ)   /* 30720 */
#define NQKV  768
#define CTXLD (HEADS*SEQ)   /* 2560 */

// ---------------- scratch (device globals: no allocation allowed) ----------
__device__ __nv_bfloat16 g_a_hi[NROWS*DIM], g_a_lo[NROWS*DIM];   // LN out split
__device__ __nv_bfloat16 g_wt_hi[NQKV*DIM], g_wt_lo[NQKV*DIM];   // W^T [n][k]
__device__ __nv_bfloat16 g_q_hi[NROWS*DIM], g_q_lo[NROWS*DIM];
__device__ __nv_bfloat16 g_k_hi[NROWS*DIM], g_k_lo[NROWS*DIM];
__device__ __nv_bfloat16 g_v_hi[NROWS*DIM], g_v_lo[NROWS*DIM];
__device__ float g_o[NROWS*DIM];

// ---------------- helpers ----------------------------------------------------
__device__ __forceinline__ uint32_t smem_u32(const void* p) {
    uint32_t a;
    asm("{ .reg .u64 t; cvta.to.shared.u64 t, %1; cvt.u32.u64 %0, t; }"
        : "=r"(a) : "l"(p));
    return a;
}

#define LDSM4(R, A)                                                           \
    asm volatile("ldmatrix.sync.aligned.m8n8.x4.shared.b16 {%0,%1,%2,%3}, [%4];" \
                 : "=r"((R)[0]), "=r"((R)[1]), "=r"((R)[2]), "=r"((R)[3])     \
                 : "r"(A))
#define LDSM2(R, A)                                                           \
    asm volatile("ldmatrix.sync.aligned.m8n8.x2.shared.b16 {%0,%1}, [%2];"    \
                 : "=r"((R)[0]), "=r"((R)[1]) : "r"(A))
#define LDSM2T(R, A)                                                          \
    asm volatile("ldmatrix.sync.aligned.m8n8.x2.trans.shared.b16 {%0,%1}, [%2];" \
                 : "=r"((R)[0]), "=r"((R)[1]) : "r"(A))
#define MMA16816(C, A, B)                                                     \
    asm volatile("mma.sync.aligned.m16n8k16.row.col.f32.bf16.bf16.f32 "       \
                 "{%0,%1,%2,%3},{%4,%5,%6,%7},{%8,%9},{%0,%1,%2,%3};"         \
                 : "+f"((C)[0]), "+f"((C)[1]), "+f"((C)[2]), "+f"((C)[3])     \
                 : "r"((A)[0]), "r"((A)[1]), "r"((A)[2]), "r"((A)[3]),        \
                   "r"((B)[0]), "r"((B)[1]))

__device__ __forceinline__ void split_bf16(float v, __nv_bfloat16& h, __nv_bfloat16& l)
{
    h = __float2bfloat16(v);
    l = __float2bfloat16(v - __bfloat162float(h));
}

// xs row (Bi, n)  ->  offset into the 7D x tensor (elems = innermost size)
__device__ __forceinline__ size_t x_offset(int Bi, int n, int elems)
{
    int b  = Bi / 48, xy = Bi % 48;
    int gx = xy >> 3, gy = xy & 7;
    int l  = n >> 6,  r  = n & 63;
    int w1 = r >> 3,  w2 = r & 7;
    return ((((((size_t)b*5 + l)*6 + gx)*8 + gy)*8 + w1)*8 + w2) * (size_t)elems;
}

// ---------------- kernel 0: weight transpose + bf16 split -------------------
__global__ __launch_bounds__(256)
void wprep_kernel(const float* __restrict__ wq, const float* __restrict__ wkv)
{
    int idx = blockIdx.x * 256 + threadIdx.x;    // 0 .. 768*256-1
    int n = idx >> 8;        // output col 0..767
    int k = idx & 255;
    float w = (n < 256) ? wq[(size_t)k * 256 + n]
                        : wkv[(size_t)k * 512 + (n - 256)];
    __nv_bfloat16 h, l;
    split_bf16(w, h, l);
    g_wt_hi[idx] = h;
    g_wt_lo[idx] = l;
}

// ---------------- kernel 1: gather-transpose + LayerNorm + bf16 split -------
__global__ __launch_bounds__(256)
void ln_kernel(const float* __restrict__ x,
               const float* __restrict__ gamma,
               const float* __restrict__ beta)
{
    int row = blockIdx.x;                 // 0..30719 = Bi*320 + n
    int Bi  = row / SEQ;
    int n   = row % SEQ;
    size_t xoff = x_offset(Bi, n, DIM);

    int d = threadIdx.x;                  // 0..255
    float v = x[xoff + d];

    float s1 = v, s2 = v * v;
    #pragma unroll
    for (int off = 16; off > 0; off >>= 1) {
        s1 += __shfl_xor_sync(0xffffffff, s1, off);
        s2 += __shfl_xor_sync(0xffffffff, s2, off);
    }
    __shared__ float sh1[8], sh2[8];
    int wid = d >> 5, lid = d & 31;
    if (lid == 0) { sh1[wid] = s1; sh2[wid] = s2; }
    __syncthreads();
    if (wid == 0) {
        float a  = (lid < 8) ? sh1[lid] : 0.f;
        float b2 = (lid < 8) ? sh2[lid] : 0.f;
        #pragma unroll
        for (int off = 4; off > 0; off >>= 1) {
            a  += __shfl_xor_sync(0xffffffff, a,  off);
            b2 += __shfl_xor_sync(0xffffffff, b2, off);
        }
        if (lid == 0) { sh1[0] = a; sh2[0] = b2; }
    }
    __syncthreads();
    float mu  = sh1[0] * (1.0f / DIM);
    float var = sh2[0] * (1.0f / DIM) - mu * mu;
    float rs  = rsqrtf(var + 1e-5f);
    float y   = (v - mu) * rs * gamma[d] + beta[d];
    __nv_bfloat16 h, l;
    split_bf16(y, h, l);
    g_a_hi[(size_t)row * DIM + d] = h;
    g_a_lo[(size_t)row * DIM + d] = l;
}

// ---------------- kernel 2: QKV projection (bf16 split mma.sync) ------------
// C(30720x768) = A(30720x256) @ W'(256x768); CTA tile 128x128, warp 32x64.
__global__ __launch_bounds__(256)
void qkv_mma(void)
{
    __shared__ __align__(16) __nv_bfloat16 sAh[128][24];   // pitch 48B
    __shared__ __align__(16) __nv_bfloat16 sAl[128][24];
    __shared__ __align__(16) __nv_bfloat16 sBh[128][24];
    __shared__ __align__(16) __nv_bfloat16 sBl[128][24];

    int tid = threadIdx.x;
    int w = tid >> 5, lane = tid & 31;
    int bx = blockIdx.x;                  // 0..5 (N tile; x fastest -> A reuse in L2)
    int row0 = blockIdx.y * 128;
    int col0 = bx * 128;

    int wm = w >> 1;                      // 0..3 -> rows wm*32 (2 m-tiles)
    int wn = w & 1;                       // 0..1 -> cols wn*64 (8 n-tiles)

    uint32_t aAh = smem_u32(&sAh[0][0]);
    uint32_t aAl = smem_u32(&sAl[0][0]);
    uint32_t aBh = smem_u32(&sBh[0][0]);
    uint32_t aBl = smem_u32(&sBl[0][0]);

    int lr16 = lane & 15, lk16 = (lane >> 4) * 16;        // x4 addressing
    int lr8  = lane & 7,  lk8  = ((lane >> 3) & 1) * 16;  // x2 addressing

    float c[2][8][4];
    #pragma unroll
    for (int i = 0; i < 2; i++)
        #pragma unroll
        for (int j = 0; j < 8; j++)
            #pragma unroll
            for (int q = 0; q < 4; q++) c[i][j][q] = 0.f;

    int r = tid >> 1, hf = tid & 1;

    for (int ks = 0; ks < 16; ks++) {
        int k0 = ks * 16;
        {
            size_t ga = (size_t)(row0 + r) * 256 + k0 + hf * 8;
            size_t gb = (size_t)(col0 + r) * 256 + k0 + hf * 8;
            *(uint4*)&sAh[r][hf * 8] = *(const uint4*)(g_a_hi + ga);
            *(uint4*)&sAl[r][hf * 8] = *(const uint4*)(g_a_lo + ga);
            *(uint4*)&sBh[r][hf * 8] = *(const uint4*)(g_wt_hi + gb);
            *(uint4*)&sBl[r][hf * 8] = *(const uint4*)(g_wt_lo + gb);
        }
        __syncthreads();

        uint32_t ah[2][4], al[2][4], bb[8][2];
        #pragma unroll
        for (int mi = 0; mi < 2; mi++) {
            uint32_t ra = (uint32_t)((wm*32 + mi*16 + lr16) * 48 + lk16);
            LDSM4(ah[mi], aAh + ra);
            LDSM4(al[mi], aAl + ra);
        }
        #pragma unroll
        for (int ni = 0; ni < 8; ni++) {
            uint32_t rb = (uint32_t)((wn*64 + ni*8 + lr8) * 48 + lk8);
            LDSM2(bb[ni], aBh + rb);
        }
        #pragma unroll
        for (int mi = 0; mi < 2; mi++)
            #pragma unroll
            for (int ni = 0; ni < 8; ni++) {
                MMA16816(c[mi][ni], ah[mi], bb[ni]);   // Ah*Bh
                MMA16816(c[mi][ni], al[mi], bb[ni]);   // Al*Bh
            }
        #pragma unroll
        for (int ni = 0; ni < 8; ni++) {
            uint32_t rb = (uint32_t)((wn*64 + ni*8 + lr8) * 48 + lk8);
            LDSM2(bb[ni], aBl + rb);
        }
        #pragma unroll
        for (int mi = 0; mi < 2; mi++)
            #pragma unroll
            for (int ni = 0; ni < 8; ni++)
                MMA16816(c[mi][ni], ah[mi], bb[ni]);   // Ah*Bl
        __syncthreads();
    }

    // epilogue: split + store bf16 hi/lo into q/k/v
    __nv_bfloat16 *dh, *dl;
    int cbase;
    if (bx < 2)      { dh = g_q_hi; dl = g_q_lo; cbase = bx * 128; }
    else if (bx < 4) { dh = g_k_hi; dl = g_k_lo; cbase = (bx - 2) * 128; }
    else             { dh = g_v_hi; dl = g_v_lo; cbase = (bx - 4) * 128; }

    int g = lane >> 2, tg = lane & 3;
    #pragma unroll
    for (int mi = 0; mi < 2; mi++) {
        #pragma unroll
        for (int ni = 0; ni < 8; ni++) {
            int cl = cbase + wn*64 + ni*8 + tg*2;
            #pragma unroll
            for (int half = 0; half < 2; half++) {
                int rowg = row0 + wm*32 + mi*16 + g + half*8;
                __nv_bfloat162 H, L;
                split_bf16(c[mi][ni][half*2+0], H.x, L.x);
                split_bf16(c[mi][ni][half*2+1], H.y, L.y);
                *(__nv_bfloat162*)(dh + (size_t)rowg * 256 + cl) = H;
                *(__nv_bfloat162*)(dl + (size_t)rowg * 256 + cl) = L;
            }
        }
    }
}

// ---------------- kernel 3: attention (flash, bf16-split mma.sync) ----------
// grid (5 n-tiles, 8 heads, 96 batch), 256 thr = 8 warps (4 m x 2 col-half)
__global__ __launch_bounds__(256)
void attn_mma(const float* __restrict__ ctx)
{
    __shared__ __align__(16) __nv_bfloat16 sP[2][64][72];  // P hi/lo (Q at start)
    __shared__ __align__(16) __nv_bfloat16 sK[2][64][40];  // K hi/lo [m][d]
    __shared__ __align__(16) __nv_bfloat16 sV[2][64][40];  // V hi/lo [m][d]
    __shared__ float pmax[2][64];
    __shared__ float psum[2][64];

    int tid = threadIdx.x;
    int w = tid >> 5, lane = tid & 31;
    int wm = w >> 1, wn = w & 1;
    int g = lane >> 2, tg = lane & 3;
    int lr16 = lane & 15, lk16 = (lane >> 4) * 16;
    int lr8  = lane & 7,  lk8  = ((lane >> 3) & 1) * 16;

    int nt = blockIdx.x, h = blockIdx.y, Bi = blockIdx.z;
    int n0 = nt * 64;
    size_t rowbase = (size_t)Bi * SEQ;

    uint32_t aP0 = smem_u32(&sP[0][0][0]);
    uint32_t aP1 = smem_u32(&sP[1][0][0]);
    uint32_t aK0 = smem_u32(&sK[0][0][0]);
    uint32_t aK1 = smem_u32(&sK[1][0][0]);
    uint32_t aV0 = smem_u32(&sV[0][0][0]);
    uint32_t aV1 = smem_u32(&sV[1][0][0]);

    // ---- Q tile -> sP region, then into registers (held whole kernel) ----
    {
        int r = tid >> 2, q = tid & 3;
        size_t go = (rowbase + n0 + r) * 256 + h * 32 + q * 8;
        *(uint4*)&sP[0][r][q * 8] = *(const uint4*)(g_q_hi + go);
        *(uint4*)&sP[1][r][q * 8] = *(const uint4*)(g_q_lo + go);
    }
    __syncthreads();
    uint32_t qh[2][4], ql[2][4];
    #pragma unroll
    for (int kk = 0; kk < 2; kk++) {
        uint32_t ra = (uint32_t)((wm*16 + lr16) * 144 + lk16 + kk*32);
        LDSM4(qh[kk], aP0 + ra);
        LDSM4(ql[kk], aP1 + ra);
    }

    const float* ctxb = ctx + (size_t)Bi * SEQ * CTXLD + (size_t)h * SEQ;

    float o[2][4];
    #pragma unroll
    for (int vi = 0; vi < 2; vi++)
        #pragma unroll
        for (int q = 0; q < 4; q++) o[vi][q] = 0.f;
    float m_lo = -1e30f, m_hi = -1e30f, l_lo = 0.f, l_hi = 0.f;

    int rl = wm*16 + g, rh = rl + 8;

    for (int m0 = 0; m0 < SEQ; m0 += 64) {
        __syncthreads();                       // prev chunk fully consumed
        {
            int r = tid >> 2, q = tid & 3;
            size_t go = (rowbase + m0 + r) * 256 + h * 32 + q * 8;
            *(uint4*)&sK[0][r][q * 8] = *(const uint4*)(g_k_hi + go);
            *(uint4*)&sK[1][r][q * 8] = *(const uint4*)(g_k_lo + go);
            *(uint4*)&sV[0][r][q * 8] = *(const uint4*)(g_v_hi + go);
            *(uint4*)&sV[1][r][q * 8] = *(const uint4*)(g_v_lo + go);
        }
        __syncthreads();

        // ---- S = bias + Q K^T (warp: rows wm*16..+15, cols wn*32..+31) ----
        float s[4][4];
        #pragma unroll
        for (int ni = 0; ni < 4; ni++) {
            int colm = m0 + wn*32 + ni*8 + tg*2;
            float2 b0 = *(const float2*)(ctxb + (size_t)(n0 + rl) * CTXLD + colm);
            float2 b1 = *(const float2*)(ctxb + (size_t)(n0 + rh) * CTXLD + colm);
            s[ni][0] = b0.x; s[ni][1] = b0.y; s[ni][2] = b1.x; s[ni][3] = b1.y;
        }
        #pragma unroll
        for (int kk = 0; kk < 2; kk++) {
            uint32_t bh[4][2], bl[4][2];
            #pragma unroll
            for (int ni = 0; ni < 4; ni++) {
                uint32_t rb = (uint32_t)((wn*32 + ni*8 + lr8) * 80 + lk8 + kk*32);
                LDSM2(bh[ni], aK0 + rb);
                LDSM2(bl[ni], aK1 + rb);
            }
            #pragma unroll
            for (int ni = 0; ni < 4; ni++) {
                MMA16816(s[ni], qh[kk], bh[ni]);
                MMA16816(s[ni], ql[kk], bh[ni]);
                MMA16816(s[ni], qh[kk], bl[ni]);
            }
        }

        // ---- online softmax (two rows per lane: rl, rh) ----
        float mx0 = s[0][0], mx1 = s[0][2];
        #pragma unroll
        for (int ni = 0; ni < 4; ni++) {
            mx0 = fmaxf(mx0, fmaxf(s[ni][0], s[ni][1]));
            mx1 = fmaxf(mx1, fmaxf(s[ni][2], s[ni][3]));
        }
        mx0 = fmaxf(mx0, __shfl_xor_sync(0xffffffff, mx0, 1));
        mx0 = fmaxf(mx0, __shfl_xor_sync(0xffffffff, mx0, 2));
        mx1 = fmaxf(mx1, __shfl_xor_sync(0xffffffff, mx1, 1));
        mx1 = fmaxf(mx1, __shfl_xor_sync(0xffffffff, mx1, 2));
        if (tg == 0) { pmax[wn][rl] = mx0; pmax[wn][rh] = mx1; }
        __syncthreads();

        float mn0 = fmaxf(m_lo, fmaxf(pmax[0][rl], pmax[1][rl]));
        float mn1 = fmaxf(m_hi, fmaxf(pmax[0][rh], pmax[1][rh]));
        float cor0 = __expf(m_lo - mn0);
        float cor1 = __expf(m_hi - mn1);
        m_lo = mn0; m_hi = mn1;

        float su0 = 0.f, su1 = 0.f;
        #pragma unroll
        for (int ni = 0; ni < 4; ni++) {
            float p0 = __expf(s[ni][0] - mn0);
            float p1 = __expf(s[ni][1] - mn0);
            float p2 = __expf(s[ni][2] - mn1);
            float p3 = __expf(s[ni][3] - mn1);
            su0 += p0 + p1; su1 += p2 + p3;
            int colk = wn*32 + ni*8 + tg*2;
            __nv_bfloat162 H0, L0, H1, L1;
            split_bf16(p0, H0.x, L0.x);
            split_bf16(p1, H0.y, L0.y);
            split_bf16(p2, H1.x, L1.x);
            split_bf16(p3, H1.y, L1.y);
            *(__nv_bfloat162*)&sP[0][rl][colk] = H0;
            *(__nv_bfloat162*)&sP[0][rh][colk] = H1;
            *(__nv_bfloat162*)&sP[1][rl][colk] = L0;
            *(__nv_bfloat162*)&sP[1][rh][colk] = L1;
        }
        su0 += __shfl_xor_sync(0xffffffff, su0, 1);
        su0 += __shfl_xor_sync(0xffffffff, su0, 2);
        su1 += __shfl_xor_sync(0xffffffff, su1, 1);
        su1 += __shfl_xor_sync(0xffffffff, su1, 2);
        if (tg == 0) { psum[wn][rl] = su0; psum[wn][rh] = su1; }
        __syncthreads();

        l_lo = l_lo * cor0 + psum[0][rl] + psum[1][rl];
        l_hi = l_hi * cor1 + psum[0][rh] + psum[1][rh];
        #pragma unroll
        for (int vi = 0; vi < 2; vi++) {
            o[vi][0] *= cor0; o[vi][1] *= cor0;
            o[vi][2] *= cor1; o[vi][3] *= cor1;
        }

        // ---- O += P @ V  (warp: rows wm*16..+15, d-cols wn*16..+15) ----
        #pragma unroll
        for (int kk = 0; kk < 4; kk++) {
            uint32_t ph[4], pl[4];
            uint32_t ra = (uint32_t)((wm*16 + lr16) * 144 + lk16 + kk*32);
            LDSM4(ph, aP0 + ra);
            LDSM4(pl, aP1 + ra);
            #pragma unroll
            for (int vi = 0; vi < 2; vi++) {
                uint32_t vhf[2], vlf[2];
                uint32_t rb = (uint32_t)((kk*16 + lr16) * 80 + (wn*16 + vi*8) * 2);
                LDSM2T(vhf, aV0 + rb);
                LDSM2T(vlf, aV1 + rb);
                MMA16816(o[vi], ph, vhf);
                MMA16816(o[vi], pl, vhf);
                MMA16816(o[vi], ph, vlf);
            }
        }
    }

    float inv0 = 1.f / l_lo, inv1 = 1.f / l_hi;
    #pragma unroll
    for (int vi = 0; vi < 2; vi++) {
        int col = h*32 + wn*16 + vi*8 + tg*2;
        *(float2*)(g_o + (rowbase + n0 + rl) * 256 + col) =
            make_float2(o[vi][0] * inv0, o[vi][1] * inv0);
        *(float2*)(g_o + (rowbase + n0 + rh) * 256 + col) =
            make_float2(o[vi][2] * inv1, o[vi][3] * inv1);
    }
}

// ---------------- kernel 4: output projection + scatter ---------------------
// out(30720 x 32) = g_o(30720 x 256) @ w_out(256 x 32); 1 row per thread
__global__ __launch_bounds__(128)
void outproj_kernel(const float* __restrict__ wout, float* __restrict__ out)
{
    __shared__ __align__(16) float ws[DIM * DHEAD];
    int tid = threadIdx.x;
    for (int i = tid * 4; i < DIM * DHEAD; i += 128 * 4)
        *(float4*)&ws[i] = *(const float4*)&wout[i];
    __syncthreads();

    int row = blockIdx.x * 128 + tid;
    const float* arow = g_o + (size_t)row * DIM;

    float acc[32];
    #pragma unroll
    for (int j = 0; j < 32; j++) acc[j] = 0.f;

    for (int k4 = 0; k4 < DIM; k4 += 4) {
        float4 a = *(const float4*)(arow + k4);
        float av[4] = {a.x, a.y, a.z, a.w};
        #pragma unroll
        for (int kk = 0; kk < 4; kk++) {
            #pragma unroll
            for (int j4 = 0; j4 < 8; j4++) {
                float4 wv = *(const float4*)&ws[(k4 + kk) * DHEAD + j4 * 4];
                acc[j4*4+0] = fmaf(av[kk], wv.x, acc[j4*4+0]);
                acc[j4*4+1] = fmaf(av[kk], wv.y, acc[j4*4+1]);
                acc[j4*4+2] = fmaf(av[kk], wv.z, acc[j4*4+2]);
                acc[j4*4+3] = fmaf(av[kk], wv.w, acc[j4*4+3]);
            }
        }
    }

    int Bi = row / SEQ, n = row % SEQ;
    size_t off = x_offset(Bi, n, DHEAD);
    #pragma unroll
    for (int j4 = 0; j4 < 8; j4++)
        *(float4*)(out + off + j4 * 4) =
            make_float4(acc[j4*4], acc[j4*4+1], acc[j4*4+2], acc[j4*4+3]);
}

// ---------------- launch ----------------------------------------------------
extern "C" void kernel_launch(void* const* d_in, const int* in_sizes, int n_in,
                              void* d_out, int out_size)
{
    (void)out_size;
    // expected order: x, context, w_q, w_kv, w_out, ln_g, ln_b
    int ix = 0, ictx = 1, iwq = 2, iwkv = 3, iwout = 4, ig = 5, ib = 6;
    int g_seen = -1;
    for (int i = 0; i < n_in; i++) {
        switch (in_sizes[i]) {
            case 7864320:  ix = i;    break;
            case 78643200: ictx = i;  break;
            case 65536:    iwq = i;   break;
            case 131072:   iwkv = i;  break;
            case 8192:     iwout = i; break;
            case 256:
                if (g_seen < 0) { ig = i; g_seen = i; } else { ib = i; }
                break;
            default: break;
        }
    }

    const float* x    = (const float*)d_in[ix];
    const float* ctx  = (const float*)d_in[ictx];
    const float* wq   = (const float*)d_in[iwq];
    const float* wkv  = (const float*)d_in[iwkv];
    const float* wout = (const float*)d_in[iwout];
    const float* lng  = (const float*)d_in[ig];
    const float* lnb  = (const float*)d_in[ib];
    float* out = (float*)d_out;

    wprep_kernel<<<NQKV, 256>>>(wq, wkv);
    ln_kernel<<<NROWS, 256>>>(x, lng, lnb);

    dim3 g2(6, 240);
    qkv_mma<<<g2, 256>>>();

    dim3 g3(5, HEADS, BATCH);
    attn_mma<<<g3, 256>>>(ctx);

    outproj_kernel<<<240, 128>>>(wout, out);
}

// round 10
// speedup vs baseline: 1.5830x; 1.0071x over previous
#include <cuda_runtime.h>
#include <cuda_bf16.h>
#include <cstdint>

#define BATCH 96
#define SEQ   320
#define DIM   256
#define HEADS 8
#define DHEAD 32
#define NROWS (BATCH*SEQ)   /* 30720 */
#define NQKV  768
#define CTXLD (HEADS*SEQ)   /* 2560 */

// ---------------- scratch (device globals: no allocation allowed) ----------
__device__ __nv_bfloat16 g_a_hi[NROWS*DIM], g_a_lo[NROWS*DIM];   // LN out split
__device__ __nv_bfloat16 g_wt_hi[NQKV*DIM], g_wt_lo[NQKV*DIM];   // W^T [n][k]
__device__ __nv_bfloat16 g_q_hi[NROWS*DIM], g_q_lo[NROWS*DIM];
__device__ __nv_bfloat16 g_k_hi[NROWS*DIM], g_k_lo[NROWS*DIM];
__device__ __nv_bfloat16 g_v_hi[NROWS*DIM], g_v_lo[NROWS*DIM];
__device__ float g_o[NROWS*DIM];

// ---------------- helpers ----------------------------------------------------
__device__ __forceinline__ uint32_t smem_u32(const void* p) {
    uint32_t a;
    asm("{ .reg .u64 t; cvta.to.shared.u64 t, %1; cvt.u32.u64 %0, t; }"
        : "=r"(a) : "l"(p));
    return a;
}

#define LDSM4(R, A)                                                           \
    asm volatile("ldmatrix.sync.aligned.m8n8.x4.shared.b16 {%0,%1,%2,%3}, [%4];" \
                 : "=r"((R)[0]), "=r"((R)[1]), "=r"((R)[2]), "=r"((R)[3])     \
                 : "r"(A))
#define LDSM2(R, A)                                                           \
    asm volatile("ldmatrix.sync.aligned.m8n8.x2.shared.b16 {%0,%1}, [%2];"    \
                 : "=r"((R)[0]), "=r"((R)[1]) : "r"(A))
#define LDSM2T(R, A)                                                          \
    asm volatile("ldmatrix.sync.aligned.m8n8.x2.trans.shared.b16 {%0,%1}, [%2];" \
                 : "=r"((R)[0]), "=r"((R)[1]) : "r"(A))
#define MMA16816(C, A, B)                                                     \
    asm volatile("mma.sync.aligned.m16n8k16.row.col.f32.bf16.bf16.f32 "       \
                 "{%0,%1,%2,%3},{%4,%5,%6,%7},{%8,%9},{%0,%1,%2,%3};"         \
                 : "+f"((C)[0]), "+f"((C)[1]), "+f"((C)[2]), "+f"((C)[3])     \
                 : "r"((A)[0]), "r"((A)[1]), "r"((A)[2]), "r"((A)[3]),        \
                   "r"((B)[0]), "r"((B)[1]))

#define CP16(dst, src)                                                        \
    asm volatile("cp.async.cg.shared.global [%0], [%1], 16;"                  \
                 :: "r"(dst), "l"(src) : "memory")
#define CP_COMMIT() asm volatile("cp.async.commit_group;" ::: "memory")
#define CP_WAIT1()  asm volatile("cp.async.wait_group 1;" ::: "memory")
#define CP_WAIT0()  asm volatile("cp.async.wait_group 0;" ::: "memory")

__device__ __forceinline__ void split_bf16(float v, __nv_bfloat16& h, __nv_bfloat16& l)
{
    h = __float2bfloat16(v);
    l = __float2bfloat16(v - __bfloat162float(h));
}
// pack two fp32 into {hi-bf16 pair, lo-bf16 pair} uint32 regs (x = low half)
__device__ __forceinline__ void pack_split2(float a, float b, uint32_t& hi, uint32_t& lo)
{
    __nv_bfloat162 H, L;
    split_bf16(a, H.x, L.x);
    split_bf16(b, H.y, L.y);
    hi = *(uint32_t*)&H;
    lo = *(uint32_t*)&L;
}

// xs row (Bi, n)  ->  offset into the 7D x tensor (elems = innermost size)
__device__ __forceinline__ size_t x_offset(int Bi, int n, int elems)
{
    int b  = Bi / 48, xy = Bi % 48;
    int gx = xy >> 3, gy = xy & 7;
    int l  = n >> 6,  r  = n & 63;
    int w1 = r >> 3,  w2 = r & 7;
    return ((((((size_t)b*5 + l)*6 + gx)*8 + gy)*8 + w1)*8 + w2) * (size_t)elems;
}

// ---------------- kernel 0: weight transpose + bf16 split -------------------
__global__ __launch_bounds__(256)
void wprep_kernel(const float* __restrict__ wq, const float* __restrict__ wkv)
{
    int idx = blockIdx.x * 256 + threadIdx.x;    // 0 .. 768*256-1
    int n = idx >> 8;
    int k = idx & 255;
    float w = (n < 256) ? wq[(size_t)k * 256 + n]
                        : wkv[(size_t)k * 512 + (n - 256)];
    __nv_bfloat16 h, l;
    split_bf16(w, h, l);
    g_wt_hi[idx] = h;
    g_wt_lo[idx] = l;
}

// ---------------- kernel 1: gather-transpose + LayerNorm + bf16 split -------
__global__ __launch_bounds__(256)
void ln_kernel(const float* __restrict__ x,
               const float* __restrict__ gamma,
               const float* __restrict__ beta)
{
    int row = blockIdx.x;
    int Bi  = row / SEQ;
    int n   = row % SEQ;
    size_t xoff = x_offset(Bi, n, DIM);

    int d = threadIdx.x;
    float v = x[xoff + d];

    float s1 = v, s2 = v * v;
    #pragma unroll
    for (int off = 16; off > 0; off >>= 1) {
        s1 += __shfl_xor_sync(0xffffffff, s1, off);
        s2 += __shfl_xor_sync(0xffffffff, s2, off);
    }
    __shared__ float sh1[8], sh2[8];
    int wid = d >> 5, lid = d & 31;
    if (lid == 0) { sh1[wid] = s1; sh2[wid] = s2; }
    __syncthreads();
    if (wid == 0) {
        float a  = (lid < 8) ? sh1[lid] : 0.f;
        float b2 = (lid < 8) ? sh2[lid] : 0.f;
        #pragma unroll
        for (int off = 4; off > 0; off >>= 1) {
            a  += __shfl_xor_sync(0xffffffff, a,  off);
            b2 += __shfl_xor_sync(0xffffffff, b2, off);
        }
        if (lid == 0) { sh1[0] = a; sh2[0] = b2; }
    }
    __syncthreads();
    float mu  = sh1[0] * (1.0f / DIM);
    float var = sh2[0] * (1.0f / DIM) - mu * mu;
    float rs  = rsqrtf(var + 1e-5f);
    float y   = (v - mu) * rs * gamma[d] + beta[d];
    __nv_bfloat16 h, l;
    split_bf16(y, h, l);
    g_a_hi[(size_t)row * DIM + d] = h;
    g_a_lo[(size_t)row * DIM + d] = l;
}

// ---------------- kernel 2: QKV projection (bf16 split, cp.async pipeline) --
// C(30720x768) = A(30720x256) @ W'(256x768); CTA tile 128x128, warp 32x64.
__global__ __launch_bounds__(256)
void qkv_mma(void)
{
    __shared__ __nv_bfloat16 sAh[2][128][24];   // 2-stage, pitch 48B
    __shared__ __nv_bfloat16 sAl[2][128][24];
    __shared__ __nv_bfloat16 sBh[2][128][24];
    __shared__ __nv_bfloat16 sBl[2][128][24];

    int tid = threadIdx.x;
    int w = tid >> 5, lane = tid & 31;
    int bx = blockIdx.x;                  // 0..5 (N tile)
    int row0 = blockIdx.y * 128;
    int col0 = bx * 128;

    int wm = w >> 1;
    int wn = w & 1;

    uint32_t aAh = smem_u32(&sAh[0][0][0]);
    uint32_t aAl = smem_u32(&sAl[0][0][0]);
    uint32_t aBh = smem_u32(&sBh[0][0][0]);
    uint32_t aBl = smem_u32(&sBl[0][0][0]);

    int lr16 = lane & 15, lk16 = (lane >> 4) * 16;
    int lr8  = lane & 7,  lk8  = ((lane >> 3) & 1) * 16;

    float c[2][8][4];
    #pragma unroll
    for (int i = 0; i < 2; i++)
        #pragma unroll
        for (int j = 0; j < 8; j++)
            #pragma unroll
            for (int q = 0; q < 4; q++) c[i][j][q] = 0.f;

    int r = tid >> 1, hf = tid & 1;
    size_t gA = (size_t)(row0 + r) * 256 + hf * 8;
    size_t gB = (size_t)(col0 + r) * 256 + hf * 8;
    uint32_t sOfs = (uint32_t)(r * 48 + hf * 16);

    // prologue: stage 0
    CP16(aAh + sOfs, g_a_hi  + gA);
    CP16(aAl + sOfs, g_a_lo  + gA);
    CP16(aBh + sOfs, g_wt_hi + gB);
    CP16(aBl + sOfs, g_wt_lo + gB);
    CP_COMMIT();

    for (int ks = 0; ks < 16; ks++) {
        int stg = ks & 1;
        if (ks < 15) {
            int nst = (ks + 1) & 1;
            uint32_t so = sOfs + (uint32_t)nst * 6144;
            size_t ko = (size_t)(ks + 1) * 16;
            CP16(aAh + so, g_a_hi  + gA + ko);
            CP16(aAl + so, g_a_lo  + gA + ko);
            CP16(aBh + so, g_wt_hi + gB + ko);
            CP16(aBl + so, g_wt_lo + gB + ko);
            CP_COMMIT();
            CP_WAIT1();
        } else {
            CP_WAIT0();
        }
        __syncthreads();

        uint32_t base = (uint32_t)stg * 6144;
        uint32_t ah[2][4], al[2][4], bb[8][2];
        #pragma unroll
        for (int mi = 0; mi < 2; mi++) {
            uint32_t ra = base + (uint32_t)((wm*32 + mi*16 + lr16) * 48 + lk16);
            LDSM4(ah[mi], aAh + ra);
            LDSM4(al[mi], aAl + ra);
        }
        #pragma unroll
        for (int ni = 0; ni < 8; ni++) {
            uint32_t rb = base + (uint32_t)((wn*64 + ni*8 + lr8) * 48 + lk8);
            LDSM2(bb[ni], aBh + rb);
        }
        #pragma unroll
        for (int mi = 0; mi < 2; mi++)
            #pragma unroll
            for (int ni = 0; ni < 8; ni++) {
                MMA16816(c[mi][ni], ah[mi], bb[ni]);   // Ah*Bh
                MMA16816(c[mi][ni], al[mi], bb[ni]);   // Al*Bh
            }
        #pragma unroll
        for (int ni = 0; ni < 8; ni++) {
            uint32_t rb = base + (uint32_t)((wn*64 + ni*8 + lr8) * 48 + lk8);
            LDSM2(bb[ni], aBl + rb);
        }
        #pragma unroll
        for (int mi = 0; mi < 2; mi++)
            #pragma unroll
            for (int ni = 0; ni < 8; ni++)
                MMA16816(c[mi][ni], ah[mi], bb[ni]);   // Ah*Bl
        __syncthreads();
    }

    // epilogue: split + store bf16 hi/lo into q/k/v
    __nv_bfloat16 *dh, *dl;
    int cbase;
    if (bx < 2)      { dh = g_q_hi; dl = g_q_lo; cbase = bx * 128; }
    else if (bx < 4) { dh = g_k_hi; dl = g_k_lo; cbase = (bx - 2) * 128; }
    else             { dh = g_v_hi; dl = g_v_lo; cbase = (bx - 4) * 128; }

    int g = lane >> 2, tg = lane & 3;
    #pragma unroll
    for (int mi = 0; mi < 2; mi++) {
        #pragma unroll
        for (int ni = 0; ni < 8; ni++) {
            int cl = cbase + wn*64 + ni*8 + tg*2;
            #pragma unroll
            for (int half = 0; half < 2; half++) {
                int rowg = row0 + wm*32 + mi*16 + g + half*8;
                uint32_t H, L;
                pack_split2(c[mi][ni][half*2+0], c[mi][ni][half*2+1], H, L);
                *(uint32_t*)(dh + (size_t)rowg * 256 + cl) = H;
                *(uint32_t*)(dl + (size_t)rowg * 256 + cl) = L;
            }
        }
    }
}

// ---------------- kernel 3: attention (flash, register-P, bf16 split) -------
// grid (5 n-tiles, 8 heads, 96 batch), 256 thr = 8 warps (4 m x 2 m-col half)
// Each warp: 16 q-rows x 32 m-cols; P stays in registers (C-frag == A-frag).
// Partial O (full 32 d per warp) reduced across the 2 wn warps at the end.
__global__ __launch_bounds__(256)
void attn_mma(const float* __restrict__ ctx)
{
    __shared__ __align__(16) __nv_bfloat16 sK[2][64][40];  // K hi/lo [m][d]
    __shared__ __align__(16) __nv_bfloat16 sV[2][64][40];  // V hi/lo [m][d]
    __shared__ __align__(16) __nv_bfloat16 sQ[2][64][40];  // Q staging; reused
    __shared__ float pmax[2][64];
    __shared__ float psum[2][64];

    float* sOf = (float*)&sQ[0][0][0];                     // 64 x 34 reduce buf

    int tid = threadIdx.x;
    int w = tid >> 5, lane = tid & 31;
    int wm = w >> 1, wn = w & 1;
    int g = lane >> 2, tg = lane & 3;
    int lr16 = lane & 15, lk16 = (lane >> 4) * 16;
    int lr8  = lane & 7,  lk8  = ((lane >> 3) & 1) * 16;

    int nt = blockIdx.x, h = blockIdx.y, Bi = blockIdx.z;
    int n0 = nt * 64;
    size_t rowbase = (size_t)Bi * SEQ;

    uint32_t aK0 = smem_u32(&sK[0][0][0]);
    uint32_t aK1 = smem_u32(&sK[1][0][0]);
    uint32_t aV0 = smem_u32(&sV[0][0][0]);
    uint32_t aV1 = smem_u32(&sV[1][0][0]);
    uint32_t aQ0 = smem_u32(&sQ[0][0][0]);
    uint32_t aQ1 = smem_u32(&sQ[1][0][0]);

    // cp.async lane mapping for K/V tile fills (16B per thread per tensor-half)
    int cr = tid >> 2, cq = tid & 3;
    uint32_t kvOfs = (uint32_t)(cr * 80 + cq * 16);        // 40 bf16 = 80B pitch

    // ---- Q tile -> staging -> registers (held whole kernel) ----
    {
        size_t go = (rowbase + n0 + cr) * 256 + h * 32 + cq * 8;
        CP16(aQ0 + kvOfs, g_q_hi + go);
        CP16(aQ1 + kvOfs, g_q_lo + go);
        CP_COMMIT();
        CP_WAIT0();
    }
    __syncthreads();
    uint32_t qh[2][4], ql[2][4];
    #pragma unroll
    for (int kk = 0; kk < 2; kk++) {
        uint32_t ra = (uint32_t)((wm*16 + lr16) * 80 + lk16 + kk*32);
        LDSM4(qh[kk], aQ0 + ra);
        LDSM4(ql[kk], aQ1 + ra);
    }
    __syncthreads();   // staging consumed (sQ reused as sOf at the end)

    const float* ctxb = ctx + (size_t)Bi * SEQ * CTXLD + (size_t)h * SEQ;

    float o[4][4];     // vi (d 8-col tile) x 4 ; partial over this warp's m-half
    #pragma unroll
    for (int vi = 0; vi < 4; vi++)
        #pragma unroll
        for (int q = 0; q < 4; q++) o[vi][q] = 0.f;
    float m_lo = -1e30f, m_hi = -1e30f, l_lo = 0.f, l_hi = 0.f;

    int rl = wm*16 + g, rh = rl + 8;

    for (int m0 = 0; m0 < SEQ; m0 += 64) {
        // ---- bias loads issued FIRST: overlap DRAM latency with K/V fill ----
        float s[4][4];
        #pragma unroll
        for (int ni = 0; ni < 4; ni++) {
            int colm = m0 + wn*32 + ni*8 + tg*2;
            float2 b0 = *(const float2*)(ctxb + (size_t)(n0 + rl) * CTXLD + colm);
            float2 b1 = *(const float2*)(ctxb + (size_t)(n0 + rh) * CTXLD + colm);
            s[ni][0] = b0.x; s[ni][1] = b0.y; s[ni][2] = b1.x; s[ni][3] = b1.y;
        }

        __syncthreads();                       // prev K/V fully consumed
        {
            size_t go = (rowbase + m0 + cr) * 256 + h * 32 + cq * 8;
            CP16(aK0 + kvOfs, g_k_hi + go);
            CP16(aK1 + kvOfs, g_k_lo + go);
            CP16(aV0 + kvOfs, g_v_hi + go);
            CP16(aV1 + kvOfs, g_v_lo + go);
            CP_COMMIT();
            CP_WAIT0();
        }
        __syncthreads();

        // ---- S = bias + Q K^T (warp: rows wm*16..+15, m-cols wn*32..+31) ----
        #pragma unroll
        for (int kk = 0; kk < 2; kk++) {
            uint32_t bh[4][2], bl[4][2];
            #pragma unroll
            for (int ni = 0; ni < 4; ni++) {
                uint32_t rb = (uint32_t)((wn*32 + ni*8 + lr8) * 80 + lk8 + kk*32);
                LDSM2(bh[ni], aK0 + rb);
                LDSM2(bl[ni], aK1 + rb);
            }
            #pragma unroll
            for (int ni = 0; ni < 4; ni++) {
                MMA16816(s[ni], qh[kk], bh[ni]);
                MMA16816(s[ni], ql[kk], bh[ni]);
                MMA16816(s[ni], qh[kk], bl[ni]);
            }
        }

        // ---- online softmax (two rows per lane: rl, rh) ----
        float mx0 = s[0][0], mx1 = s[0][2];
        #pragma unroll
        for (int ni = 0; ni < 4; ni++) {
            mx0 = fmaxf(mx0, fmaxf(s[ni][0], s[ni][1]));
            mx1 = fmaxf(mx1, fmaxf(s[ni][2], s[ni][3]));
        }
        mx0 = fmaxf(mx0, __shfl_xor_sync(0xffffffff, mx0, 1));
        mx0 = fmaxf(mx0, __shfl_xor_sync(0xffffffff, mx0, 2));
        mx1 = fmaxf(mx1, __shfl_xor_sync(0xffffffff, mx1, 1));
        mx1 = fmaxf(mx1, __shfl_xor_sync(0xffffffff, mx1, 2));
        if (tg == 0) { pmax[wn][rl] = mx0; pmax[wn][rh] = mx1; }
        __syncthreads();

        float mn0 = fmaxf(m_lo, fmaxf(pmax[0][rl], pmax[1][rl]));
        float mn1 = fmaxf(m_hi, fmaxf(pmax[0][rh], pmax[1][rh]));
        float cor0 = __expf(m_lo - mn0);
        float cor1 = __expf(m_hi - mn1);
        m_lo = mn0; m_hi = mn1;

        // exp in place; accumulate local sums
        float su0 = 0.f, su1 = 0.f;
        #pragma unroll
        for (int ni = 0; ni < 4; ni++) {
            s[ni][0] = __expf(s[ni][0] - mn0);
            s[ni][1] = __expf(s[ni][1] - mn0);
            s[ni][2] = __expf(s[ni][2] - mn1);
            s[ni][3] = __expf(s[ni][3] - mn1);
            su0 += s[ni][0] + s[ni][1];
            su1 += s[ni][2] + s[ni][3];
        }
        su0 += __shfl_xor_sync(0xffffffff, su0, 1);
        su0 += __shfl_xor_sync(0xffffffff, su0, 2);
        su1 += __shfl_xor_sync(0xffffffff, su1, 1);
        su1 += __shfl_xor_sync(0xffffffff, su1, 2);
        if (tg == 0) { psum[wn][rl] = su0; psum[wn][rh] = su1; }

        // rescale running O while sums land
        #pragma unroll
        for (int vi = 0; vi < 4; vi++) {
            o[vi][0] *= cor0; o[vi][1] *= cor0;
            o[vi][2] *= cor1; o[vi][3] *= cor1;
        }
        __syncthreads();
        l_lo = l_lo * cor0 + psum[0][rl] + psum[1][rl];
        l_hi = l_hi * cor1 + psum[0][rh] + psum[1][rh];

        // ---- O += P @ V : P C-frags ARE the A-frags (no smem round-trip) ----
        #pragma unroll
        for (int kk = 0; kk < 2; kk++) {
            uint32_t ph[4], pl[4];
            pack_split2(s[2*kk][0],   s[2*kk][1],   ph[0], pl[0]);
            pack_split2(s[2*kk][2],   s[2*kk][3],   ph[1], pl[1]);
            pack_split2(s[2*kk+1][0], s[2*kk+1][1], ph[2], pl[2]);
            pack_split2(s[2*kk+1][2], s[2*kk+1][3], ph[3], pl[3]);
            #pragma unroll
            for (int vi = 0; vi < 4; vi++) {
                uint32_t vhf[2], vlf[2];
                uint32_t rb = (uint32_t)((wn*32 + kk*16 + lr16) * 80 + vi*16);
                LDSM2T(vhf, aV0 + rb);
                LDSM2T(vlf, aV1 + rb);
                MMA16816(o[vi], ph, vhf);
                MMA16816(o[vi], pl, vhf);
                MMA16816(o[vi], ph, vlf);
            }
        }
    }

    // ---- cross-warp (wn) O reduction + normalize + store ----
    __syncthreads();                 // everyone done with sQ-region reads
    if (wn == 1) {
        #pragma unroll
        for (int vi = 0; vi < 4; vi++) {
            int d = vi*8 + tg*2;
            *(float2*)&sOf[rl * 34 + d] = make_float2(o[vi][0], o[vi][1]);
            *(float2*)&sOf[rh * 34 + d] = make_float2(o[vi][2], o[vi][3]);
        }
    }
    __syncthreads();
    if (wn == 0) {
        float inv0 = 1.f / l_lo, inv1 = 1.f / l_hi;
        #pragma unroll
        for (int vi = 0; vi < 4; vi++) {
            int d = vi*8 + tg*2;
            float2 p0 = *(const float2*)&sOf[rl * 34 + d];
            float2 p1 = *(const float2*)&sOf[rh * 34 + d];
            int col = h*32 + d;
            *(float2*)(g_o + (rowbase + n0 + rl) * 256 + col) =
                make_float2((o[vi][0] + p0.x) * inv0, (o[vi][1] + p0.y) * inv0);
            *(float2*)(g_o + (rowbase + n0 + rh) * 256 + col) =
                make_float2((o[vi][2] + p1.x) * inv1, (o[vi][3] + p1.y) * inv1);
        }
    }
}

// ---------------- kernel 4: output projection + scatter ---------------------
__global__ __launch_bounds__(128)
void outproj_kernel(const float* __restrict__ wout, float* __restrict__ out)
{
    __shared__ __align__(16) float ws[DIM * DHEAD];
    int tid = threadIdx.x;
    for (int i = tid * 4; i < DIM * DHEAD; i += 128 * 4)
        *(float4*)&ws[i] = *(const float4*)&wout[i];
    __syncthreads();

    int row = blockIdx.x * 128 + tid;
    const float* arow = g_o + (size_t)row * DIM;

    float acc[32];
    #pragma unroll
    for (int j = 0; j < 32; j++) acc[j] = 0.f;

    for (int k4 = 0; k4 < DIM; k4 += 4) {
        float4 a = *(const float4*)(arow + k4);
        float av[4] = {a.x, a.y, a.z, a.w};
        #pragma unroll
        for (int kk = 0; kk < 4; kk++) {
            #pragma unroll
            for (int j4 = 0; j4 < 8; j4++) {
                float4 wv = *(const float4*)&ws[(k4 + kk) * DHEAD + j4 * 4];
                acc[j4*4+0] = fmaf(av[kk], wv.x, acc[j4*4+0]);
                acc[j4*4+1] = fmaf(av[kk], wv.y, acc[j4*4+1]);
                acc[j4*4+2] = fmaf(av[kk], wv.z, acc[j4*4+2]);
                acc[j4*4+3] = fmaf(av[kk], wv.w, acc[j4*4+3]);
            }
        }
    }

    int Bi = row / SEQ, n = row % SEQ;
    size_t off = x_offset(Bi, n, DHEAD);
    #pragma unroll
    for (int j4 = 0; j4 < 8; j4++)
        *(float4*)(out + off + j4 * 4) =
            make_float4(acc[j4*4], acc[j4*4+1], acc[j4*4+2], acc[j4*4+3]);
}

// ---------------- launch ----------------------------------------------------
extern "C" void kernel_launch(void* const* d_in, const int* in_sizes, int n_in,
                              void* d_out, int out_size)
{
    (void)out_size;
    // expected order: x, context, w_q, w_kv, w_out, ln_g, ln_b
    int ix = 0, ictx = 1, iwq = 2, iwkv = 3, iwout = 4, ig = 5, ib = 6;
    int g_seen = -1;
    for (int i = 0; i < n_in; i++) {
        switch (in_sizes[i]) {
            case 7864320:  ix = i;    break;
            case 78643200: ictx = i;  break;
            case 65536:    iwq = i;   break;
            case 131072:   iwkv = i;  break;
            case 8192:     iwout = i; break;
            case 256:
                if (g_seen < 0) { ig = i; g_seen = i; } else { ib = i; }
                break;
            default: break;
        }
    }

    const float* x    = (const float*)d_in[ix];
    const float* ctx  = (const float*)d_in[ictx];
    const float* wq   = (const float*)d_in[iwq];
    const float* wkv  = (const float*)d_in[iwkv];
    const float* wout = (const float*)d_in[iwout];
    const float* lng  = (const float*)d_in[ig];
    const float* lnb  = (const float*)d_in[ib];
    float* out = (float*)d_out;

    wprep_kernel<<<NQKV, 256>>>(wq, wkv);
    ln_kernel<<<NROWS, 256>>>(x, lng, lnb);

    dim3 g2(6, 240);
    qkv_mma<<<g2, 256>>>();

    dim3 g3(5, HEADS, BATCH);
    attn_mma<<<g3, 256>>>(ctx);

    outproj_kernel<<<240, 128>>>(wout, out);
}

// round 11
// speedup vs baseline: 1.7509x; 1.1061x over previous
#include <cuda_runtime.h>
#include <cuda_bf16.h>
#include <cstdint>

#define BATCH 96
#define SEQ   320
#define DIM   256
#define HEADS 8
#define DHEAD 32
#define NROWS (BATCH*SEQ)   /* 30720 */
#define NQKV  768
#define CTXLD (HEADS*SEQ)   /* 2560 */

// ---------------- scratch (device globals: no allocation allowed) ----------
__device__ __nv_bfloat16 g_a_hi[NROWS*DIM], g_a_lo[NROWS*DIM];   // LN out split
__device__ __nv_bfloat16 g_wt_hi[NQKV*DIM], g_wt_lo[NQKV*DIM];   // W^T [n][k]
__device__ __nv_bfloat16 g_q_hi[NROWS*DIM], g_q_lo[NROWS*DIM];
__device__ __nv_bfloat16 g_k_hi[NROWS*DIM], g_k_lo[NROWS*DIM];
__device__ __nv_bfloat16 g_v_hi[NROWS*DIM], g_v_lo[NROWS*DIM];
__device__ float g_o[NROWS*DIM];

// ---------------- helpers ----------------------------------------------------
__device__ __forceinline__ uint32_t smem_u32(const void* p) {
    uint32_t a;
    asm("{ .reg .u64 t; cvta.to.shared.u64 t, %1; cvt.u32.u64 %0, t; }"
        : "=r"(a) : "l"(p));
    return a;
}

#define LDSM4(R, A)                                                           \
    asm volatile("ldmatrix.sync.aligned.m8n8.x4.shared.b16 {%0,%1,%2,%3}, [%4];" \
                 : "=r"((R)[0]), "=r"((R)[1]), "=r"((R)[2]), "=r"((R)[3])     \
                 : "r"(A))
#define LDSM4T(R, A)                                                          \
    asm volatile("ldmatrix.sync.aligned.m8n8.x4.trans.shared.b16 {%0,%1,%2,%3}, [%4];" \
                 : "=r"((R)[0]), "=r"((R)[1]), "=r"((R)[2]), "=r"((R)[3])     \
                 : "r"(A))
#define LDSM2(R, A)                                                           \
    asm volatile("ldmatrix.sync.aligned.m8n8.x2.shared.b16 {%0,%1}, [%2];"    \
                 : "=r"((R)[0]), "=r"((R)[1]) : "r"(A))
#define MMA16816(C, A, B)                                                     \
    asm volatile("mma.sync.aligned.m16n8k16.row.col.f32.bf16.bf16.f32 "       \
                 "{%0,%1,%2,%3},{%4,%5,%6,%7},{%8,%9},{%0,%1,%2,%3};"         \
                 : "+f"((C)[0]), "+f"((C)[1]), "+f"((C)[2]), "+f"((C)[3])     \
                 : "r"((A)[0]), "r"((A)[1]), "r"((A)[2]), "r"((A)[3]),        \
                   "r"((B)[0]), "r"((B)[1]))

#define CP16(dst, src)                                                        \
    asm volatile("cp.async.cg.shared.global [%0], [%1], 16;"                  \
                 :: "r"(dst), "l"(src) : "memory")
#define CP_COMMIT() asm volatile("cp.async.commit_group;" ::: "memory")
#define CP_WAIT1()  asm volatile("cp.async.wait_group 1;" ::: "memory")
#define CP_WAIT0()  asm volatile("cp.async.wait_group 0;" ::: "memory")

__device__ __forceinline__ void split_bf16(float v, __nv_bfloat16& h, __nv_bfloat16& l)
{
    h = __float2bfloat16(v);
    l = __float2bfloat16(v - __bfloat162float(h));
}
// pack two fp32 into {hi-bf16 pair, lo-bf16 pair} uint32 regs (x = low half)
__device__ __forceinline__ void pack_split2(float a, float b, uint32_t& hi, uint32_t& lo)
{
    __nv_bfloat162 H, L;
    split_bf16(a, H.x, L.x);
    split_bf16(b, H.y, L.y);
    hi = *(uint32_t*)&H;
    lo = *(uint32_t*)&L;
}

// xs row (Bi, n)  ->  offset into the 7D x tensor (elems = innermost size)
__device__ __forceinline__ size_t x_offset(int Bi, int n, int elems)
{
    int b  = Bi / 48, xy = Bi % 48;
    int gx = xy >> 3, gy = xy & 7;
    int l  = n >> 6,  r  = n & 63;
    int w1 = r >> 3,  w2 = r & 7;
    return ((((((size_t)b*5 + l)*6 + gx)*8 + gy)*8 + w1)*8 + w2) * (size_t)elems;
}

// ---------------- kernel 0: weight transpose + bf16 split -------------------
__global__ __launch_bounds__(256)
void wprep_kernel(const float* __restrict__ wq, const float* __restrict__ wkv)
{
    int idx = blockIdx.x * 256 + threadIdx.x;    // 0 .. 768*256-1
    int n = idx >> 8;
    int k = idx & 255;
    float w = (n < 256) ? wq[(size_t)k * 256 + n]
                        : wkv[(size_t)k * 512 + (n - 256)];
    __nv_bfloat16 h, l;
    split_bf16(w, h, l);
    g_wt_hi[idx] = h;
    g_wt_lo[idx] = l;
}

// ---------------- kernel 1: gather-transpose + LayerNorm + bf16 split -------
__global__ __launch_bounds__(256)
void ln_kernel(const float* __restrict__ x,
               const float* __restrict__ gamma,
               const float* __restrict__ beta)
{
    int row = blockIdx.x;
    int Bi  = row / SEQ;
    int n   = row % SEQ;
    size_t xoff = x_offset(Bi, n, DIM);

    int d = threadIdx.x;
    float v = x[xoff + d];

    float s1 = v, s2 = v * v;
    #pragma unroll
    for (int off = 16; off > 0; off >>= 1) {
        s1 += __shfl_xor_sync(0xffffffff, s1, off);
        s2 += __shfl_xor_sync(0xffffffff, s2, off);
    }
    __shared__ float sh1[8], sh2[8];
    int wid = d >> 5, lid = d & 31;
    if (lid == 0) { sh1[wid] = s1; sh2[wid] = s2; }
    __syncthreads();
    if (wid == 0) {
        float a  = (lid < 8) ? sh1[lid] : 0.f;
        float b2 = (lid < 8) ? sh2[lid] : 0.f;
        #pragma unroll
        for (int off = 4; off > 0; off >>= 1) {
            a  += __shfl_xor_sync(0xffffffff, a,  off);
            b2 += __shfl_xor_sync(0xffffffff, b2, off);
        }
        if (lid == 0) { sh1[0] = a; sh2[0] = b2; }
    }
    __syncthreads();
    float mu  = sh1[0] * (1.0f / DIM);
    float var = sh2[0] * (1.0f / DIM) - mu * mu;
    float rs  = rsqrtf(var + 1e-5f);
    float y   = (v - mu) * rs * gamma[d] + beta[d];
    __nv_bfloat16 h, l;
    split_bf16(y, h, l);
    g_a_hi[(size_t)row * DIM + d] = h;
    g_a_lo[(size_t)row * DIM + d] = l;
}

// ---------------- kernel 2: QKV projection (bf16 split, cp.async pipeline) --
// C(30720x768) = A(30720x256) @ W'(256x768); CTA tile 128x128, warp 32x64.
__global__ __launch_bounds__(256)
void qkv_mma(void)
{
    __shared__ __nv_bfloat16 sAh[2][128][24];   // 2-stage, pitch 48B
    __shared__ __nv_bfloat16 sAl[2][128][24];
    __shared__ __nv_bfloat16 sBh[2][128][24];
    __shared__ __nv_bfloat16 sBl[2][128][24];

    int tid = threadIdx.x;
    int w = tid >> 5, lane = tid & 31;
    int bx = blockIdx.x;                  // 0..5 (N tile)
    int row0 = blockIdx.y * 128;
    int col0 = bx * 128;

    int wm = w >> 1;
    int wn = w & 1;

    uint32_t aAh = smem_u32(&sAh[0][0][0]);
    uint32_t aAl = smem_u32(&sAl[0][0][0]);
    uint32_t aBh = smem_u32(&sBh[0][0][0]);
    uint32_t aBl = smem_u32(&sBl[0][0][0]);

    int lr16 = lane & 15, lk16 = (lane >> 4) * 16;
    int lr8  = lane & 7,  lk8  = ((lane >> 3) & 1) * 16;

    float c[2][8][4];
    #pragma unroll
    for (int i = 0; i < 2; i++)
        #pragma unroll
        for (int j = 0; j < 8; j++)
            #pragma unroll
            for (int q = 0; q < 4; q++) c[i][j][q] = 0.f;

    int r = tid >> 1, hf = tid & 1;
    size_t gA = (size_t)(row0 + r) * 256 + hf * 8;
    size_t gB = (size_t)(col0 + r) * 256 + hf * 8;
    uint32_t sOfs = (uint32_t)(r * 48 + hf * 16);

    // prologue: stage 0
    CP16(aAh + sOfs, g_a_hi  + gA);
    CP16(aAl + sOfs, g_a_lo  + gA);
    CP16(aBh + sOfs, g_wt_hi + gB);
    CP16(aBl + sOfs, g_wt_lo + gB);
    CP_COMMIT();

    for (int ks = 0; ks < 16; ks++) {
        int stg = ks & 1;
        if (ks < 15) {
            int nst = (ks + 1) & 1;
            uint32_t so = sOfs + (uint32_t)nst * 6144;
            size_t ko = (size_t)(ks + 1) * 16;
            CP16(aAh + so, g_a_hi  + gA + ko);
            CP16(aAl + so, g_a_lo  + gA + ko);
            CP16(aBh + so, g_wt_hi + gB + ko);
            CP16(aBl + so, g_wt_lo + gB + ko);
            CP_COMMIT();
            CP_WAIT1();
        } else {
            CP_WAIT0();
        }
        __syncthreads();

        uint32_t base = (uint32_t)stg * 6144;
        uint32_t ah[2][4], al[2][4], bb[8][2];
        #pragma unroll
        for (int mi = 0; mi < 2; mi++) {
            uint32_t ra = base + (uint32_t)((wm*32 + mi*16 + lr16) * 48 + lk16);
            LDSM4(ah[mi], aAh + ra);
            LDSM4(al[mi], aAl + ra);
        }
        #pragma unroll
        for (int ni = 0; ni < 8; ni++) {
            uint32_t rb = base + (uint32_t)((wn*64 + ni*8 + lr8) * 48 + lk8);
            LDSM2(bb[ni], aBh + rb);
        }
        #pragma unroll
        for (int mi = 0; mi < 2; mi++)
            #pragma unroll
            for (int ni = 0; ni < 8; ni++) {
                MMA16816(c[mi][ni], ah[mi], bb[ni]);   // Ah*Bh
                MMA16816(c[mi][ni], al[mi], bb[ni]);   // Al*Bh
            }
        #pragma unroll
        for (int ni = 0; ni < 8; ni++) {
            uint32_t rb = base + (uint32_t)((wn*64 + ni*8 + lr8) * 48 + lk8);
            LDSM2(bb[ni], aBl + rb);
        }
        #pragma unroll
        for (int mi = 0; mi < 2; mi++)
            #pragma unroll
            for (int ni = 0; ni < 8; ni++)
                MMA16816(c[mi][ni], ah[mi], bb[ni]);   // Ah*Bl
        __syncthreads();
    }

    // epilogue: split + store bf16 hi/lo into q/k/v
    __nv_bfloat16 *dh, *dl;
    int cbase;
    if (bx < 2)      { dh = g_q_hi; dl = g_q_lo; cbase = bx * 128; }
    else if (bx < 4) { dh = g_k_hi; dl = g_k_lo; cbase = (bx - 2) * 128; }
    else             { dh = g_v_hi; dl = g_v_lo; cbase = (bx - 4) * 128; }

    int g = lane >> 2, tg = lane & 3;
    #pragma unroll
    for (int mi = 0; mi < 2; mi++) {
        #pragma unroll
        for (int ni = 0; ni < 8; ni++) {
            int cl = cbase + wn*64 + ni*8 + tg*2;
            #pragma unroll
            for (int half = 0; half < 2; half++) {
                int rowg = row0 + wm*32 + mi*16 + g + half*8;
                uint32_t H, L;
                pack_split2(c[mi][ni][half*2+0], c[mi][ni][half*2+1], H, L);
                *(uint32_t*)(dh + (size_t)rowg * 256 + cl) = H;
                *(uint32_t*)(dl + (size_t)rowg * 256 + cl) = L;
            }
        }
    }
}

// ---------------- kernel 3: attention (flash, warp-private softmax) ---------
// grid (5 n-tiles, 8 heads, 96 batch), 128 thr = 4 warps.
// Warp wm owns q-rows wm*16..+15 x ALL 64 m-cols -> softmax is warp-local.
// K/V double-buffered via cp.async; ONE __syncthreads per m-chunk.
__global__ __launch_bounds__(128)
void attn_mma(const float* __restrict__ ctx)
{
    __shared__ __align__(16) __nv_bfloat16 sK[2][2][64][40];  // [stage][hi/lo]
    __shared__ __align__(16) __nv_bfloat16 sV[2][2][64][40];

    int tid = threadIdx.x;
    int lane = tid & 31, wm = tid >> 5;
    int g = lane >> 2, tg = lane & 3;
    int lr16 = lane & 15, lk16 = (lane >> 4) * 16;

    int nt = blockIdx.x, h = blockIdx.y, Bi = blockIdx.z;
    int n0 = nt * 64;
    size_t rowbase = (size_t)Bi * SEQ;

    uint32_t aK[2][2], aV[2][2];
    #pragma unroll
    for (int s = 0; s < 2; s++) {
        #pragma unroll
        for (int hl = 0; hl < 2; hl++) {
            aK[s][hl] = smem_u32(&sK[s][hl][0][0]);
            aV[s][hl] = smem_u32(&sV[s][hl][0][0]);
        }
    }

    // cp.async mapping: row = tid>>1, 32-byte half cb
    int cr = tid >> 1;
    int cb = (tid & 1) * 32;
    uint32_t so = (uint32_t)(cr * 80 + cb);
    int ce = cb >> 1;                    // element offset within row (bf16)

    // ldmatrix x4 lane addressing (K pairs / V-trans pairs)
    int l7 = lane & 7, lb3 = (lane >> 3) & 1, lb4 = lane >> 4;

    // ---- prologue: Q staged through stage-1 K region, then K/V stage 0 ----
    {
        size_t gq = (rowbase + n0 + cr) * 256 + h * 32 + ce;
        CP16(aK[1][0] + so,      g_q_hi + gq);
        CP16(aK[1][0] + so + 16, g_q_hi + gq + 8);
        CP16(aK[1][1] + so,      g_q_lo + gq);
        CP16(aK[1][1] + so + 16, g_q_lo + gq + 8);
        CP_COMMIT();
        size_t gb = (rowbase + 0 + cr) * 256 + h * 32 + ce;
        CP16(aK[0][0] + so,      g_k_hi + gb);
        CP16(aK[0][0] + so + 16, g_k_hi + gb + 8);
        CP16(aK[0][1] + so,      g_k_lo + gb);
        CP16(aK[0][1] + so + 16, g_k_lo + gb + 8);
        CP16(aV[0][0] + so,      g_v_hi + gb);
        CP16(aV[0][0] + so + 16, g_v_hi + gb + 8);
        CP16(aV[0][1] + so,      g_v_lo + gb);
        CP16(aV[0][1] + so + 16, g_v_lo + gb + 8);
        CP_COMMIT();
    }
    CP_WAIT1();              // Q group complete (stage-0 K/V may still fly)
    __syncthreads();

    uint32_t qh[2][4], ql[2][4];
    #pragma unroll
    for (int kk = 0; kk < 2; kk++) {
        uint32_t ra = (uint32_t)((wm*16 + lr16) * 80 + lk16 + kk*32);
        LDSM4(qh[kk], aK[1][0] + ra);
        LDSM4(ql[kk], aK[1][1] + ra);
    }

    const float* ctxb = ctx + (size_t)Bi * SEQ * CTXLD + (size_t)h * SEQ;

    float o[4][4];
    #pragma unroll
    for (int vi = 0; vi < 4; vi++)
        #pragma unroll
        for (int q = 0; q < 4; q++) o[vi][q] = 0.f;
    float m_lo = -1e30f, m_hi = -1e30f, l_lo = 0.f, l_hi = 0.f;

    int rl = wm*16 + g, rh = rl + 8;
    const float* bias_l = ctxb + (size_t)(n0 + rl) * CTXLD;
    const float* bias_h = ctxb + (size_t)(n0 + rh) * CTXLD;

    for (int it = 0; it < 5; it++) {
        int m0 = it * 64, stg = it & 1;

        // ---- bias loads first (DRAM latency overlaps wait+issue+QK) ----
        float s[8][4];
        #pragma unroll
        for (int ni = 0; ni < 8; ni++) {
            int colm = m0 + ni*8 + tg*2;
            float2 b0 = *(const float2*)(bias_l + colm);
            float2 b1 = *(const float2*)(bias_h + colm);
            s[ni][0] = b0.x; s[ni][1] = b0.y; s[ni][2] = b1.x; s[ni][3] = b1.y;
        }

        CP_WAIT0();          // stage stg data (issued last iteration) ready
        __syncthreads();     // all warps past previous reads; data visible

        if (it < 4) {        // issue next stage into the buffer just freed
            size_t gb = (rowbase + m0 + 64 + cr) * 256 + h * 32 + ce;
            int ns = stg ^ 1;
            CP16(aK[ns][0] + so,      g_k_hi + gb);
            CP16(aK[ns][0] + so + 16, g_k_hi + gb + 8);
            CP16(aK[ns][1] + so,      g_k_lo + gb);
            CP16(aK[ns][1] + so + 16, g_k_lo + gb + 8);
            CP16(aV[ns][0] + so,      g_v_hi + gb);
            CP16(aV[ns][0] + so + 16, g_v_hi + gb + 8);
            CP16(aV[ns][1] + so,      g_v_lo + gb);
            CP16(aV[ns][1] + so + 16, g_v_lo + gb + 8);
            CP_COMMIT();
        }

        // ---- S = bias + Q K^T : 8 n-tiles, x4-pair ldmatrix for K ----
        #pragma unroll
        for (int kk = 0; kk < 2; kk++) {
            uint32_t bh[8][2], bl[8][2];
            #pragma unroll
            for (int pi = 0; pi < 4; pi++) {
                uint32_t ad = (uint32_t)((pi*16 + lb4*8 + l7) * 80
                                         + kk*32 + lb3*16);
                uint32_t t[4];
                LDSM4(t, aK[stg][0] + ad);
                bh[2*pi][0] = t[0]; bh[2*pi][1] = t[1];
                bh[2*pi+1][0] = t[2]; bh[2*pi+1][1] = t[3];
                LDSM4(t, aK[stg][1] + ad);
                bl[2*pi][0] = t[0]; bl[2*pi][1] = t[1];
                bl[2*pi+1][0] = t[2]; bl[2*pi+1][1] = t[3];
            }
            #pragma unroll
            for (int ni = 0; ni < 8; ni++) {
                MMA16816(s[ni], qh[kk], bh[ni]);
                MMA16816(s[ni], ql[kk], bh[ni]);
                MMA16816(s[ni], qh[kk], bl[ni]);
            }
        }

        // ---- warp-private online softmax (rows rl, rh) ----
        float mx0 = s[0][0], mx1 = s[0][2];
        #pragma unroll
        for (int ni = 0; ni < 8; ni++) {
            mx0 = fmaxf(mx0, fmaxf(s[ni][0], s[ni][1]));
            mx1 = fmaxf(mx1, fmaxf(s[ni][2], s[ni][3]));
        }
        mx0 = fmaxf(mx0, __shfl_xor_sync(0xffffffff, mx0, 1));
        mx0 = fmaxf(mx0, __shfl_xor_sync(0xffffffff, mx0, 2));
        mx1 = fmaxf(mx1, __shfl_xor_sync(0xffffffff, mx1, 1));
        mx1 = fmaxf(mx1, __shfl_xor_sync(0xffffffff, mx1, 2));

        float mn0 = fmaxf(m_lo, mx0);
        float mn1 = fmaxf(m_hi, mx1);
        float cor0 = __expf(m_lo - mn0);
        float cor1 = __expf(m_hi - mn1);
        m_lo = mn0; m_hi = mn1;

        float su0 = 0.f, su1 = 0.f;
        #pragma unroll
        for (int ni = 0; ni < 8; ni++) {
            s[ni][0] = __expf(s[ni][0] - mn0);
            s[ni][1] = __expf(s[ni][1] - mn0);
            s[ni][2] = __expf(s[ni][2] - mn1);
            s[ni][3] = __expf(s[ni][3] - mn1);
            su0 += s[ni][0] + s[ni][1];
            su1 += s[ni][2] + s[ni][3];
        }
        su0 += __shfl_xor_sync(0xffffffff, su0, 1);
        su0 += __shfl_xor_sync(0xffffffff, su0, 2);
        su1 += __shfl_xor_sync(0xffffffff, su1, 1);
        su1 += __shfl_xor_sync(0xffffffff, su1, 2);
        l_lo = l_lo * cor0 + su0;
        l_hi = l_hi * cor1 + su1;

        #pragma unroll
        for (int vi = 0; vi < 4; vi++) {
            o[vi][0] *= cor0; o[vi][1] *= cor0;
            o[vi][2] *= cor1; o[vi][3] *= cor1;
        }

        // ---- O += P @ V : P C-frags ARE A-frags; x4-pair trans V loads ----
        #pragma unroll
        for (int kk = 0; kk < 4; kk++) {
            uint32_t ph[4], pl[4];
            pack_split2(s[2*kk][0],   s[2*kk][1],   ph[0], pl[0]);
            pack_split2(s[2*kk][2],   s[2*kk][3],   ph[1], pl[1]);
            pack_split2(s[2*kk+1][0], s[2*kk+1][1], ph[2], pl[2]);
            pack_split2(s[2*kk+1][2], s[2*kk+1][3], ph[3], pl[3]);
            #pragma unroll
            for (int vp = 0; vp < 2; vp++) {
                uint32_t ad = (uint32_t)((kk*16 + lb3*8 + l7) * 80
                                         + (vp*2 + lb4) * 16);
                uint32_t th[4], tl[4];
                LDSM4T(th, aV[stg][0] + ad);
                LDSM4T(tl, aV[stg][1] + ad);
                uint32_t vh0[2] = {th[0], th[1]}, vh1[2] = {th[2], th[3]};
                uint32_t vl0[2] = {tl[0], tl[1]}, vl1[2] = {tl[2], tl[3]};
                MMA16816(o[vp*2],   ph, vh0);
                MMA16816(o[vp*2],   pl, vh0);
                MMA16816(o[vp*2],   ph, vl0);
                MMA16816(o[vp*2+1], ph, vh1);
                MMA16816(o[vp*2+1], pl, vh1);
                MMA16816(o[vp*2+1], ph, vl1);
            }
        }
    }

    // ---- normalize + store (no cross-warp reduction needed) ----
    float inv0 = 1.f / l_lo, inv1 = 1.f / l_hi;
    #pragma unroll
    for (int vi = 0; vi < 4; vi++) {
        int col = h*32 + vi*8 + tg*2;
        *(float2*)(g_o + (rowbase + n0 + rl) * 256 + col) =
            make_float2(o[vi][0] * inv0, o[vi][1] * inv0);
        *(float2*)(g_o + (rowbase + n0 + rh) * 256 + col) =
            make_float2(o[vi][2] * inv1, o[vi][3] * inv1);
    }
}

// ---------------- kernel 4: output projection + scatter ---------------------
__global__ __launch_bounds__(128)
void outproj_kernel(const float* __restrict__ wout, float* __restrict__ out)
{
    __shared__ __align__(16) float ws[DIM * DHEAD];
    int tid = threadIdx.x;
    for (int i = tid * 4; i < DIM * DHEAD; i += 128 * 4)
        *(float4*)&ws[i] = *(const float4*)&wout[i];
    __syncthreads();

    int row = blockIdx.x * 128 + tid;
    const float* arow = g_o + (size_t)row * DIM;

    float acc[32];
    #pragma unroll
    for (int j = 0; j < 32; j++) acc[j] = 0.f;

    for (int k4 = 0; k4 < DIM; k4 += 4) {
        float4 a = *(const float4*)(arow + k4);
        float av[4] = {a.x, a.y, a.z, a.w};
        #pragma unroll
        for (int kk = 0; kk < 4; kk++) {
            #pragma unroll
            for (int j4 = 0; j4 < 8; j4++) {
                float4 wv = *(const float4*)&ws[(k4 + kk) * DHEAD + j4 * 4];
                acc[j4*4+0] = fmaf(av[kk], wv.x, acc[j4*4+0]);
                acc[j4*4+1] = fmaf(av[kk], wv.y, acc[j4*4+1]);
                acc[j4*4+2] = fmaf(av[kk], wv.z, acc[j4*4+2]);
                acc[j4*4+3] = fmaf(av[kk], wv.w, acc[j4*4+3]);
            }
        }
    }

    int Bi = row / SEQ, n = row % SEQ;
    size_t off = x_offset(Bi, n, DHEAD);
    #pragma unroll
    for (int j4 = 0; j4 < 8; j4++)
        *(float4*)(out + off + j4 * 4) =
            make_float4(acc[j4*4], acc[j4*4+1], acc[j4*4+2], acc[j4*4+3]);
}

// ---------------- launch ----------------------------------------------------
extern "C" void kernel_launch(void* const* d_in, const int* in_sizes, int n_in,
                              void* d_out, int out_size)
{
    (void)out_size;
    // expected order: x, context, w_q, w_kv, w_out, ln_g, ln_b
    int ix = 0, ictx = 1, iwq = 2, iwkv = 3, iwout = 4, ig = 5, ib = 6;
    int g_seen = -1;
    for (int i = 0; i < n_in; i++) {
        switch (in_sizes[i]) {
            case 7864320:  ix = i;    break;
            case 78643200: ictx = i;  break;
            case 65536:    iwq = i;   break;
            case 131072:   iwkv = i;  break;
            case 8192:     iwout = i; break;
            case 256:
                if (g_seen < 0) { ig = i; g_seen = i; } else { ib = i; }
                break;
            default: break;
        }
    }

    const float* x    = (const float*)d_in[ix];
    const float* ctx  = (const float*)d_in[ictx];
    const float* wq   = (const float*)d_in[iwq];
    const float* wkv  = (const float*)d_in[iwkv];
    const float* wout = (const float*)d_in[iwout];
    const float* lng  = (const float*)d_in[ig];
    const float* lnb  = (const float*)d_in[ib];
    float* out = (float*)d_out;

    wprep_kernel<<<NQKV, 256>>>(wq, wkv);
    ln_kernel<<<NROWS, 256>>>(x, lng, lnb);

    dim3 g2(6, 240);
    qkv_mma<<<g2, 256>>>();

    dim3 g3(5, HEADS, BATCH);
    attn_mma<<<g3, 128>>>(ctx);

    outproj_kernel<<<240, 128>>>(wout, out);
}

// round 13
// speedup vs baseline: 1.8163x; 1.0373x over previous
#include <cuda_runtime.h>
#include <cuda_bf16.h>
#include <cstdint>

#define BATCH 96
#define SEQ   320
#define DIM   256
#define HEADS 8
#define DHEAD 32
#define NROWS (BATCH*SEQ)   /* 30720 */
#define NQKV  768
#define CTXLD (HEADS*SEQ)   /* 2560 */

// ---------------- scratch (device globals: no allocation allowed) ----------
__device__ __nv_bfloat16 g_a_hi[NROWS*DIM], g_a_lo[NROWS*DIM];   // LN out split
__device__ __nv_bfloat16 g_wt_hi[NQKV*DIM], g_wt_lo[NQKV*DIM];   // W^T [n][k]
__device__ __nv_bfloat16 g_q_hi[NROWS*DIM], g_q_lo[NROWS*DIM];
__device__ __nv_bfloat16 g_k_hi[NROWS*DIM], g_k_lo[NROWS*DIM];
__device__ __nv_bfloat16 g_v_hi[NROWS*DIM], g_v_lo[NROWS*DIM];
__device__ float g_o[NROWS*DIM];

// ---------------- helpers ----------------------------------------------------
__device__ __forceinline__ uint32_t smem_u32(const void* p) {
    uint32_t a;
    asm("{ .reg .u64 t; cvta.to.shared.u64 t, %1; cvt.u32.u64 %0, t; }"
        : "=r"(a) : "l"(p));
    return a;
}

#define LDSM4(R, A)                                                           \
    asm volatile("ldmatrix.sync.aligned.m8n8.x4.shared.b16 {%0,%1,%2,%3}, [%4];" \
                 : "=r"((R)[0]), "=r"((R)[1]), "=r"((R)[2]), "=r"((R)[3])     \
                 : "r"(A))
#define LDSM4T(R, A)                                                          \
    asm volatile("ldmatrix.sync.aligned.m8n8.x4.trans.shared.b16 {%0,%1,%2,%3}, [%4];" \
                 : "=r"((R)[0]), "=r"((R)[1]), "=r"((R)[2]), "=r"((R)[3])     \
                 : "r"(A))
#define MMA16816(C, A, B)                                                     \
    asm volatile("mma.sync.aligned.m16n8k16.row.col.f32.bf16.bf16.f32 "       \
                 "{%0,%1,%2,%3},{%4,%5,%6,%7},{%8,%9},{%0,%1,%2,%3};"         \
                 : "+f"((C)[0]), "+f"((C)[1]), "+f"((C)[2]), "+f"((C)[3])     \
                 : "r"((A)[0]), "r"((A)[1]), "r"((A)[2]), "r"((A)[3]),        \
                   "r"((B)[0]), "r"((B)[1]))

#define CP16(dst, src)                                                        \
    asm volatile("cp.async.cg.shared.global [%0], [%1], 16;"                  \
                 :: "r"(dst), "l"(src) : "memory")
#define CP_COMMIT() asm volatile("cp.async.commit_group;" ::: "memory")
#define CP_WAIT1()  asm volatile("cp.async.wait_group 1;" ::: "memory")
#define CP_WAIT0()  asm volatile("cp.async.wait_group 0;" ::: "memory")

__device__ __forceinline__ void split_bf16(float v, __nv_bfloat16& h, __nv_bfloat16& l)
{
    h = __float2bfloat16(v);
    l = __float2bfloat16(v - __bfloat162float(h));
}
// pack two fp32 into {hi-bf16 pair, lo-bf16 pair} uint32 regs (x = low half)
__device__ __forceinline__ void pack_split2(float a, float b, uint32_t& hi, uint32_t& lo)
{
    __nv_bfloat162 H, L;
    split_bf16(a, H.x, L.x);
    split_bf16(b, H.y, L.y);
    hi = *(uint32_t*)&H;
    lo = *(uint32_t*)&L;
}

// xs row (Bi, n)  ->  offset into the 7D x tensor (elems = innermost size)
__device__ __forceinline__ size_t x_offset(int Bi, int n, int elems)
{
    int b  = Bi / 48, xy = Bi % 48;
    int gx = xy >> 3, gy = xy & 7;
    int l  = n >> 6,  r  = n & 63;
    int w1 = r >> 3,  w2 = r & 7;
    return ((((((size_t)b*5 + l)*6 + gx)*8 + gy)*8 + w1)*8 + w2) * (size_t)elems;
}

// ---------------- kernel 0: weight transpose + bf16 split -------------------
__global__ __launch_bounds__(256)
void wprep_kernel(const float* __restrict__ wq, const float* __restrict__ wkv)
{
    int idx = blockIdx.x * 256 + threadIdx.x;    // 0 .. 768*256-1
    int n = idx >> 8;
    int k = idx & 255;
    float w = (n < 256) ? wq[(size_t)k * 256 + n]
                        : wkv[(size_t)k * 512 + (n - 256)];
    __nv_bfloat16 h, l;
    split_bf16(w, h, l);
    g_wt_hi[idx] = h;
    g_wt_lo[idx] = l;
}

// ---------------- kernel 1: gather-transpose + LayerNorm + bf16 split -------
__global__ __launch_bounds__(256)
void ln_kernel(const float* __restrict__ x,
               const float* __restrict__ gamma,
               const float* __restrict__ beta)
{
    int row = blockIdx.x;
    int Bi  = row / SEQ;
    int n   = row % SEQ;
    size_t xoff = x_offset(Bi, n, DIM);

    int d = threadIdx.x;
    float v = x[xoff + d];

    float s1 = v, s2 = v * v;
    #pragma unroll
    for (int off = 16; off > 0; off >>= 1) {
        s1 += __shfl_xor_sync(0xffffffff, s1, off);
        s2 += __shfl_xor_sync(0xffffffff, s2, off);
    }
    __shared__ float sh1[8], sh2[8];
    int wid = d >> 5, lid = d & 31;
    if (lid == 0) { sh1[wid] = s1; sh2[wid] = s2; }
    __syncthreads();
    if (wid == 0) {
        float a  = (lid < 8) ? sh1[lid] : 0.f;
        float b2 = (lid < 8) ? sh2[lid] : 0.f;
        #pragma unroll
        for (int off = 4; off > 0; off >>= 1) {
            a  += __shfl_xor_sync(0xffffffff, a,  off);
            b2 += __shfl_xor_sync(0xffffffff, b2, off);
        }
        if (lid == 0) { sh1[0] = a; sh2[0] = b2; }
    }
    __syncthreads();
    float mu  = sh1[0] * (1.0f / DIM);
    float var = sh2[0] * (1.0f / DIM) - mu * mu;
    float rs  = rsqrtf(var + 1e-5f);
    float y   = (v - mu) * rs * gamma[d] + beta[d];
    __nv_bfloat16 h, l;
    split_bf16(y, h, l);
    g_a_hi[(size_t)row * DIM + d] = h;
    g_a_lo[(size_t)row * DIM + d] = l;
}

// ---------------- kernel 2: QKV projection (bf16 split, cp.async pipeline) --
// C(30720x768) = A(30720x256) @ W'(256x768); CTA tile 128x128, warp 32x64.
// ONE barrier per K-step: wait0 -> sync -> issue next cp -> compute.
__global__ __launch_bounds__(256)
void qkv_mma(void)
{
    __shared__ __align__(16) __nv_bfloat16 sAh[2][128][24];   // 2-stage, 48B pitch
    __shared__ __align__(16) __nv_bfloat16 sAl[2][128][24];
    __shared__ __align__(16) __nv_bfloat16 sBh[2][128][24];
    __shared__ __align__(16) __nv_bfloat16 sBl[2][128][24];

    int tid = threadIdx.x;
    int w = tid >> 5, lane = tid & 31;
    int bx = blockIdx.x;                  // 0..5 (N tile)
    int row0 = blockIdx.y * 128;
    int col0 = bx * 128;

    int wm = w >> 1;
    int wn = w & 1;

    uint32_t aAh = smem_u32(&sAh[0][0][0]);
    uint32_t aAl = smem_u32(&sAl[0][0][0]);
    uint32_t aBh = smem_u32(&sBh[0][0][0]);
    uint32_t aBl = smem_u32(&sBl[0][0][0]);

    int lr16 = lane & 15, lk16 = (lane >> 4) * 16;
    int l7 = lane & 7, lb3 = (lane >> 3) & 1, lb4 = lane >> 4;

    float c[2][8][4];
    #pragma unroll
    for (int i = 0; i < 2; i++)
        #pragma unroll
        for (int j = 0; j < 8; j++)
            #pragma unroll
            for (int q = 0; q < 4; q++) c[i][j][q] = 0.f;

    int r = tid >> 1, hf = tid & 1;
    size_t gA = (size_t)(row0 + r) * 256 + hf * 8;
    size_t gB = (size_t)(col0 + r) * 256 + hf * 8;
    uint32_t sOfs = (uint32_t)(r * 48 + hf * 16);

    // prologue: stage 0
    CP16(aAh + sOfs, g_a_hi  + gA);
    CP16(aAl + sOfs, g_a_lo  + gA);
    CP16(aBh + sOfs, g_wt_hi + gB);
    CP16(aBl + sOfs, g_wt_lo + gB);
    CP_COMMIT();

    for (int ks = 0; ks < 16; ks++) {
        int stg = ks & 1;
        CP_WAIT0();          // data for stage stg ready (issued last iter)
        __syncthreads();     // everyone past previous stage's reads

        if (ks < 15) {       // next stage into buffer just freed
            int nst = stg ^ 1;
            uint32_t so = sOfs + (uint32_t)nst * 6144;
            size_t ko = (size_t)(ks + 1) * 16;
            CP16(aAh + so, g_a_hi  + gA + ko);
            CP16(aAl + so, g_a_lo  + gA + ko);
            CP16(aBh + so, g_wt_hi + gB + ko);
            CP16(aBl + so, g_wt_lo + gB + ko);
            CP_COMMIT();
        }

        uint32_t base = (uint32_t)stg * 6144;
        uint32_t ah[2][4], al[2][4], bb[8][2];
        #pragma unroll
        for (int mi = 0; mi < 2; mi++) {
            uint32_t ra = base + (uint32_t)((wm*32 + mi*16 + lr16) * 48 + lk16);
            LDSM4(ah[mi], aAh + ra);
            LDSM4(al[mi], aAl + ra);
        }
        // B-hi: x4-pair loads (two n-tiles per ldmatrix); rows*48 +{0,16}: 16B aligned
        #pragma unroll
        for (int pi = 0; pi < 4; pi++) {
            uint32_t ad = base + (uint32_t)((wn*64 + pi*16 + lb4*8 + l7) * 48
                                            + lb3*16);
            uint32_t t[4];
            LDSM4(t, aBh + ad);
            bb[2*pi][0] = t[0]; bb[2*pi][1] = t[1];
            bb[2*pi+1][0] = t[2]; bb[2*pi+1][1] = t[3];
        }
        #pragma unroll
        for (int mi = 0; mi < 2; mi++)
            #pragma unroll
            for (int ni = 0; ni < 8; ni++) {
                MMA16816(c[mi][ni], ah[mi], bb[ni]);   // Ah*Bh
                MMA16816(c[mi][ni], al[mi], bb[ni]);   // Al*Bh
            }
        // B-lo: x4-pair loads
        #pragma unroll
        for (int pi = 0; pi < 4; pi++) {
            uint32_t ad = base + (uint32_t)((wn*64 + pi*16 + lb4*8 + l7) * 48
                                            + lb3*16);
            uint32_t t[4];
            LDSM4(t, aBl + ad);
            bb[2*pi][0] = t[0]; bb[2*pi][1] = t[1];
            bb[2*pi+1][0] = t[2]; bb[2*pi+1][1] = t[3];
        }
        #pragma unroll
        for (int mi = 0; mi < 2; mi++)
            #pragma unroll
            for (int ni = 0; ni < 8; ni++)
                MMA16816(c[mi][ni], ah[mi], bb[ni]);   // Ah*Bl
    }

    // epilogue: split + store bf16 hi/lo into q/k/v
    __nv_bfloat16 *dh, *dl;
    int cbase;
    if (bx < 2)      { dh = g_q_hi; dl = g_q_lo; cbase = bx * 128; }
    else if (bx < 4) { dh = g_k_hi; dl = g_k_lo; cbase = (bx - 2) * 128; }
    else             { dh = g_v_hi; dl = g_v_lo; cbase = (bx - 4) * 128; }

    int g = lane >> 2, tg = lane & 3;
    #pragma unroll
    for (int mi = 0; mi < 2; mi++) {
        #pragma unroll
        for (int ni = 0; ni < 8; ni++) {
            int cl = cbase + wn*64 + ni*8 + tg*2;
            #pragma unroll
            for (int half = 0; half < 2; half++) {
                int rowg = row0 + wm*32 + mi*16 + g + half*8;
                uint32_t H, L;
                pack_split2(c[mi][ni][half*2+0], c[mi][ni][half*2+1], H, L);
                *(uint32_t*)(dh + (size_t)rowg * 256 + cl) = H;
                *(uint32_t*)(dl + (size_t)rowg * 256 + cl) = L;
            }
        }
    }
}

// ---------------- kernel 3: attention (flash, warp-private softmax) ---------
// grid (5 n-tiles, 8 heads, 96 batch), 128 thr = 4 warps.
// Warp wm owns q-rows wm*16..+15 x ALL 64 m-cols -> softmax is warp-local.
// K/V double-buffered via cp.async; ONE __syncthreads per m-chunk.
// (identical to the R11 kernel that passed at 167 us)
__global__ __launch_bounds__(128)
void attn_mma(const float* __restrict__ ctx)
{
    __shared__ __align__(16) __nv_bfloat16 sK[2][2][64][40];  // [stage][hi/lo]
    __shared__ __align__(16) __nv_bfloat16 sV[2][2][64][40];

    int tid = threadIdx.x;
    int lane = tid & 31, wm = tid >> 5;
    int g = lane >> 2, tg = lane & 3;
    int lr16 = lane & 15, lk16 = (lane >> 4) * 16;

    int nt = blockIdx.x, h = blockIdx.y, Bi = blockIdx.z;
    int n0 = nt * 64;
    size_t rowbase = (size_t)Bi * SEQ;

    uint32_t aK[2][2], aV[2][2];
    #pragma unroll
    for (int s = 0; s < 2; s++) {
        #pragma unroll
        for (int hl = 0; hl < 2; hl++) {
            aK[s][hl] = smem_u32(&sK[s][hl][0][0]);
            aV[s][hl] = smem_u32(&sV[s][hl][0][0]);
        }
    }

    // cp.async mapping: row = tid>>1, 32-byte half cb
    int cr = tid >> 1;
    int cb = (tid & 1) * 32;
    uint32_t so = (uint32_t)(cr * 80 + cb);
    int ce = cb >> 1;                    // element offset within row (bf16)

    // ldmatrix x4 lane addressing (K pairs / V-trans pairs)
    int l7 = lane & 7, lb3 = (lane >> 3) & 1, lb4 = lane >> 4;

    // ---- prologue: Q staged through stage-1 K region, then K/V stage 0 ----
    {
        size_t gq = (rowbase + n0 + cr) * 256 + h * 32 + ce;
        CP16(aK[1][0] + so,      g_q_hi + gq);
        CP16(aK[1][0] + so + 16, g_q_hi + gq + 8);
        CP16(aK[1][1] + so,      g_q_lo + gq);
        CP16(aK[1][1] + so + 16, g_q_lo + gq + 8);
        CP_COMMIT();
        size_t gb = (rowbase + 0 + cr) * 256 + h * 32 + ce;
        CP16(aK[0][0] + so,      g_k_hi + gb);
        CP16(aK[0][0] + so + 16, g_k_hi + gb + 8);
        CP16(aK[0][1] + so,      g_k_lo + gb);
        CP16(aK[0][1] + so + 16, g_k_lo + gb + 8);
        CP16(aV[0][0] + so,      g_v_hi + gb);
        CP16(aV[0][0] + so + 16, g_v_hi + gb + 8);
        CP16(aV[0][1] + so,      g_v_lo + gb);
        CP16(aV[0][1] + so + 16, g_v_lo + gb + 8);
        CP_COMMIT();
    }
    CP_WAIT1();              // Q group complete (stage-0 K/V may still fly)
    __syncthreads();

    uint32_t qh[2][4], ql[2][4];
    #pragma unroll
    for (int kk = 0; kk < 2; kk++) {
        uint32_t ra = (uint32_t)((wm*16 + lr16) * 80 + lk16 + kk*32);
        LDSM4(qh[kk], aK[1][0] + ra);
        LDSM4(ql[kk], aK[1][1] + ra);
    }

    const float* ctxb = ctx + (size_t)Bi * SEQ * CTXLD + (size_t)h * SEQ;

    float o[4][4];
    #pragma unroll
    for (int vi = 0; vi < 4; vi++)
        #pragma unroll
        for (int q = 0; q < 4; q++) o[vi][q] = 0.f;
    float m_lo = -1e30f, m_hi = -1e30f, l_lo = 0.f, l_hi = 0.f;

    int rl = wm*16 + g, rh = rl + 8;
    const float* bias_l = ctxb + (size_t)(n0 + rl) * CTXLD;
    const float* bias_h = ctxb + (size_t)(n0 + rh) * CTXLD;

    for (int it = 0; it < 5; it++) {
        int m0 = it * 64, stg = it & 1;

        // ---- bias loads first (latency overlaps wait+issue+QK) ----
        float s[8][4];
        #pragma unroll
        for (int ni = 0; ni < 8; ni++) {
            int colm = m0 + ni*8 + tg*2;
            float2 b0 = *(const float2*)(bias_l + colm);
            float2 b1 = *(const float2*)(bias_h + colm);
            s[ni][0] = b0.x; s[ni][1] = b0.y; s[ni][2] = b1.x; s[ni][3] = b1.y;
        }

        CP_WAIT0();          // stage stg data (issued last iteration) ready
        __syncthreads();     // all warps past previous reads; data visible

        if (it < 4) {        // issue next stage into the buffer just freed
            size_t gb = (rowbase + m0 + 64 + cr) * 256 + h * 32 + ce;
            int ns = stg ^ 1;
            CP16(aK[ns][0] + so,      g_k_hi + gb);
            CP16(aK[ns][0] + so + 16, g_k_hi + gb + 8);
            CP16(aK[ns][1] + so,      g_k_lo + gb);
            CP16(aK[ns][1] + so + 16, g_k_lo + gb + 8);
            CP16(aV[ns][0] + so,      g_v_hi + gb);
            CP16(aV[ns][0] + so + 16, g_v_hi + gb + 8);
            CP16(aV[ns][1] + so,      g_v_lo + gb);
            CP16(aV[ns][1] + so + 16, g_v_lo + gb + 8);
            CP_COMMIT();
        }

        // ---- S = bias + Q K^T : 8 n-tiles, x4-pair ldmatrix for K ----
        #pragma unroll
        for (int kk = 0; kk < 2; kk++) {
            uint32_t bh[8][2], bl[8][2];
            #pragma unroll
            for (int pi = 0; pi < 4; pi++) {
                uint32_t ad = (uint32_t)((pi*16 + lb4*8 + l7) * 80
                                         + kk*32 + lb3*16);
                uint32_t t[4];
                LDSM4(t, aK[stg][0] + ad);
                bh[2*pi][0] = t[0]; bh[2*pi][1] = t[1];
                bh[2*pi+1][0] = t[2]; bh[2*pi+1][1] = t[3];
                LDSM4(t, aK[stg][1] + ad);
                bl[2*pi][0] = t[0]; bl[2*pi][1] = t[1];
                bl[2*pi+1][0] = t[2]; bl[2*pi+1][1] = t[3];
            }
            #pragma unroll
            for (int ni = 0; ni < 8; ni++) {
                MMA16816(s[ni], qh[kk], bh[ni]);
                MMA16816(s[ni], ql[kk], bh[ni]);
                MMA16816(s[ni], qh[kk], bl[ni]);
            }
        }

        // ---- warp-private online softmax (rows rl, rh) ----
        float mx0 = s[0][0], mx1 = s[0][2];
        #pragma unroll
        for (int ni = 0; ni < 8; ni++) {
            mx0 = fmaxf(mx0, fmaxf(s[ni][0], s[ni][1]));
            mx1 = fmaxf(mx1, fmaxf(s[ni][2], s[ni][3]));
        }
        mx0 = fmaxf(mx0, __shfl_xor_sync(0xffffffff, mx0, 1));
        mx0 = fmaxf(mx0, __shfl_xor_sync(0xffffffff, mx0, 2));
        mx1 = fmaxf(mx1, __shfl_xor_sync(0xffffffff, mx1, 1));
        mx1 = fmaxf(mx1, __shfl_xor_sync(0xffffffff, mx1, 2));

        float mn0 = fmaxf(m_lo, mx0);
        float mn1 = fmaxf(m_hi, mx1);
        float cor0 = __expf(m_lo - mn0);
        float cor1 = __expf(m_hi - mn1);
        m_lo = mn0; m_hi = mn1;

        float su0 = 0.f, su1 = 0.f;
        #pragma unroll
        for (int ni = 0; ni < 8; ni++) {
            s[ni][0] = __expf(s[ni][0] - mn0);
            s[ni][1] = __expf(s[ni][1] - mn0);
            s[ni][2] = __expf(s[ni][2] - mn1);
            s[ni][3] = __expf(s[ni][3] - mn1);
            su0 += s[ni][0] + s[ni][1];
            su1 += s[ni][2] + s[ni][3];
        }
        su0 += __shfl_xor_sync(0xffffffff, su0, 1);
        su0 += __shfl_xor_sync(0xffffffff, su0, 2);
        su1 += __shfl_xor_sync(0xffffffff, su1, 1);
        su1 += __shfl_xor_sync(0xffffffff, su1, 2);
        l_lo = l_lo * cor0 + su0;
        l_hi = l_hi * cor1 + su1;

        #pragma unroll
        for (int vi = 0; vi < 4; vi++) {
            o[vi][0] *= cor0; o[vi][1] *= cor0;
            o[vi][2] *= cor1; o[vi][3] *= cor1;
        }

        // ---- O += P @ V : P C-frags ARE A-frags; x4-pair trans V loads ----
        #pragma unroll
        for (int kk = 0; kk < 4; kk++) {
            uint32_t ph[4], pl[4];
            pack_split2(s[2*kk][0],   s[2*kk][1],   ph[0], pl[0]);
            pack_split2(s[2*kk][2],   s[2*kk][3],   ph[1], pl[1]);
            pack_split2(s[2*kk+1][0], s[2*kk+1][1], ph[2], pl[2]);
            pack_split2(s[2*kk+1][2], s[2*kk+1][3], ph[3], pl[3]);
            #pragma unroll
            for (int vp = 0; vp < 2; vp++) {
                uint32_t ad = (uint32_t)((kk*16 + lb3*8 + l7) * 80
                                         + (vp*2 + lb4) * 16);
                uint32_t th[4], tl[4];
                LDSM4T(th, aV[stg][0] + ad);
                LDSM4T(tl, aV[stg][1] + ad);
                uint32_t vh0[2] = {th[0], th[1]}, vh1[2] = {th[2], th[3]};
                uint32_t vl0[2] = {tl[0], tl[1]}, vl1[2] = {tl[2], tl[3]};
                MMA16816(o[vp*2],   ph, vh0);
                MMA16816(o[vp*2],   pl, vh0);
                MMA16816(o[vp*2],   ph, vl0);
                MMA16816(o[vp*2+1], ph, vh1);
                MMA16816(o[vp*2+1], pl, vh1);
                MMA16816(o[vp*2+1], ph, vl1);
            }
        }
    }

    // ---- normalize + store (no cross-warp reduction needed) ----
    float inv0 = 1.f / l_lo, inv1 = 1.f / l_hi;
    #pragma unroll
    for (int vi = 0; vi < 4; vi++) {
        int col = h*32 + vi*8 + tg*2;
        *(float2*)(g_o + (rowbase + n0 + rl) * 256 + col) =
            make_float2(o[vi][0] * inv0, o[vi][1] * inv0);
        *(float2*)(g_o + (rowbase + n0 + rh) * 256 + col) =
            make_float2(o[vi][2] * inv1, o[vi][3] * inv1);
    }
}

// ---------------- kernel 4: output projection + scatter ---------------------
__global__ __launch_bounds__(128)
void outproj_kernel(const float* __restrict__ wout, float* __restrict__ out)
{
    __shared__ __align__(16) float ws[DIM * DHEAD];
    int tid = threadIdx.x;
    for (int i = tid * 4; i < DIM * DHEAD; i += 128 * 4)
        *(float4*)&ws[i] = *(const float4*)&wout[i];
    __syncthreads();

    int row = blockIdx.x * 128 + tid;
    const float* arow = g_o + (size_t)row * DIM;

    float acc[32];
    #pragma unroll
    for (int j = 0; j < 32; j++) acc[j] = 0.f;

    for (int k4 = 0; k4 < DIM; k4 += 4) {
        float4 a = *(const float4*)(arow + k4);
        float av[4] = {a.x, a.y, a.z, a.w};
        #pragma unroll
        for (int kk = 0; kk < 4; kk++) {
            #pragma unroll
            for (int j4 = 0; j4 < 8; j4++) {
                float4 wv = *(const float4*)&ws[(k4 + kk) * DHEAD + j4 * 4];
                acc[j4*4+0] = fmaf(av[kk], wv.x, acc[j4*4+0]);
                acc[j4*4+1] = fmaf(av[kk], wv.y, acc[j4*4+1]);
                acc[j4*4+2] = fmaf(av[kk], wv.z, acc[j4*4+2]);
                acc[j4*4+3] = fmaf(av[kk], wv.w, acc[j4*4+3]);
            }
        }
    }

    int Bi = row / SEQ, n = row % SEQ;
    size_t off = x_offset(Bi, n, DHEAD);
    #pragma unroll
    for (int j4 = 0; j4 < 8; j4++)
        *(float4*)(out + off + j4 * 4) =
            make_float4(acc[j4*4], acc[j4*4+1], acc[j4*4+2], acc[j4*4+3]);
}

// ---------------- launch ----------------------------------------------------
extern "C" void kernel_launch(void* const* d_in, const int* in_sizes, int n_in,
                              void* d_out, int out_size)
{
    (void)out_size;
    // expected order: x, context, w_q, w_kv, w_out, ln_g, ln_b
    int ix = 0, ictx = 1, iwq = 2, iwkv = 3, iwout = 4, ig = 5, ib = 6;
    int g_seen = -1;
    for (int i = 0; i < n_in; i++) {
        switch (in_sizes[i]) {
            case 7864320:  ix = i;    break;
            case 78643200: ictx = i;  break;
            case 65536:    iwq = i;   break;
            case 131072:   iwkv = i;  break;
            case 8192:     iwout = i; break;
            case 256:
                if (g_seen < 0) { ig = i; g_seen = i; } else { ib = i; }
                break;
            default: break;
        }
    }

    const float* x    = (const float*)d_in[ix];
    const float* ctx  = (const float*)d_in[ictx];
    const float* wq   = (const float*)d_in[iwq];
    const float* wkv  = (const float*)d_in[iwkv];
    const float* wout = (const float*)d_in[iwout];
    const float* lng  = (const float*)d_in[ig];
    const float* lnb  = (const float*)d_in[ib];
    float* out = (float*)d_out;

    wprep_kernel<<<NQKV, 256>>>(wq, wkv);
    ln_kernel<<<NROWS, 256>>>(x, lng, lnb);

    dim3 g2(6, 240);
    qkv_mma<<<g2, 256>>>();

    dim3 g3(5, HEADS, BATCH);
    attn_mma<<<g3, 128>>>(ctx);

    outproj_kernel<<<240, 128>>>(wout, out);
}

// round 14
// speedup vs baseline: 2.0547x; 1.1313x over previous
#include <cuda_runtime.h>
#include <cuda_bf16.h>
#include <cstdint>

#define BATCH 96
#define SEQ   320
#define DIM   256
#define HEADS 8
#define DHEAD 32
#define NROWS (BATCH*SEQ)   /* 30720 */
#define NQKV  768
#define CTXLD (HEADS*SEQ)   /* 2560 */

// ---------------- scratch (device globals: no allocation allowed) ----------
__device__ __nv_bfloat16 g_a_hi[NROWS*DIM], g_a_lo[NROWS*DIM];   // LN out split
__device__ __nv_bfloat16 g_wt_hi[NQKV*DIM], g_wt_lo[NQKV*DIM];   // W^T [n][k]
__device__ __nv_bfloat16 g_q_hi[NROWS*DIM], g_q_lo[NROWS*DIM];
__device__ __nv_bfloat16 g_k_hi[NROWS*DIM], g_k_lo[NROWS*DIM];
__device__ __nv_bfloat16 g_v_hi[NROWS*DIM], g_v_lo[NROWS*DIM];
__device__ float g_o[NROWS*DIM];

// ---------------- helpers ----------------------------------------------------
__device__ __forceinline__ uint32_t smem_u32(const void* p) {
    uint32_t a;
    asm("{ .reg .u64 t; cvta.to.shared.u64 t, %1; cvt.u32.u64 %0, t; }"
        : "=r"(a) : "l"(p));
    return a;
}

#define LDSM4(R, A)                                                           \
    asm volatile("ldmatrix.sync.aligned.m8n8.x4.shared.b16 {%0,%1,%2,%3}, [%4];" \
                 : "=r"((R)[0]), "=r"((R)[1]), "=r"((R)[2]), "=r"((R)[3])     \
                 : "r"(A))
#define LDSM4T(R, A)                                                          \
    asm volatile("ldmatrix.sync.aligned.m8n8.x4.trans.shared.b16 {%0,%1,%2,%3}, [%4];" \
                 : "=r"((R)[0]), "=r"((R)[1]), "=r"((R)[2]), "=r"((R)[3])     \
                 : "r"(A))
#define MMA16816(C, A, B)                                                     \
    asm volatile("mma.sync.aligned.m16n8k16.row.col.f32.bf16.bf16.f32 "       \
                 "{%0,%1,%2,%3},{%4,%5,%6,%7},{%8,%9},{%0,%1,%2,%3};"         \
                 : "+f"((C)[0]), "+f"((C)[1]), "+f"((C)[2]), "+f"((C)[3])     \
                 : "r"((A)[0]), "r"((A)[1]), "r"((A)[2]), "r"((A)[3]),        \
                   "r"((B)[0]), "r"((B)[1]))

#define CP16(dst, src)                                                        \
    asm volatile("cp.async.cg.shared.global [%0], [%1], 16;"                  \
                 :: "r"(dst), "l"(src) : "memory")
#define CP_COMMIT() asm volatile("cp.async.commit_group;" ::: "memory")
#define CP_WAIT1()  asm volatile("cp.async.wait_group 1;" ::: "memory")
#define CP_WAIT0()  asm volatile("cp.async.wait_group 0;" ::: "memory")

__device__ __forceinline__ void split_bf16(float v, __nv_bfloat16& h, __nv_bfloat16& l)
{
    h = __float2bfloat16(v);
    l = __float2bfloat16(v - __bfloat162float(h));
}
// pack two fp32 into {hi-bf16 pair, lo-bf16 pair} uint32 regs (x = low half)
__device__ __forceinline__ void pack_split2(float a, float b, uint32_t& hi, uint32_t& lo)
{
    __nv_bfloat162 H, L;
    split_bf16(a, H.x, L.x);
    split_bf16(b, H.y, L.y);
    hi = *(uint32_t*)&H;
    lo = *(uint32_t*)&L;
}

// xs row (Bi, n)  ->  offset into the 7D x tensor (elems = innermost size)
__device__ __forceinline__ size_t x_offset(int Bi, int n, int elems)
{
    int b  = Bi / 48, xy = Bi % 48;
    int gx = xy >> 3, gy = xy & 7;
    int l  = n >> 6,  r  = n & 63;
    int w1 = r >> 3,  w2 = r & 7;
    return ((((((size_t)b*5 + l)*6 + gx)*8 + gy)*8 + w1)*8 + w2) * (size_t)elems;
}

// ---------------- kernel 0: weight transpose + bf16 split -------------------
__global__ __launch_bounds__(256)
void wprep_kernel(const float* __restrict__ wq, const float* __restrict__ wkv)
{
    int idx = blockIdx.x * 256 + threadIdx.x;    // 0 .. 768*256-1
    int n = idx >> 8;
    int k = idx & 255;
    float w = (n < 256) ? wq[(size_t)k * 256 + n]
                        : wkv[(size_t)k * 512 + (n - 256)];
    __nv_bfloat16 h, l;
    split_bf16(w, h, l);
    g_wt_hi[idx] = h;
    g_wt_lo[idx] = l;
}

// ---------------- kernel 1: LayerNorm, warp-per-row (shuffle-only) ----------
// 8 warps/block, 1 warp = 1 row of 256; lane holds 8 strided elements.
__global__ __launch_bounds__(256)
void ln_kernel(const float* __restrict__ x,
               const float* __restrict__ gamma,
               const float* __restrict__ beta)
{
    int wid = threadIdx.x >> 5, lane = threadIdx.x & 31;
    int row = blockIdx.x * 8 + wid;       // 0..30719
    int Bi  = row / SEQ;
    int n   = row % SEQ;
    size_t xoff = x_offset(Bi, n, DIM);

    float v[8];
    #pragma unroll
    for (int j = 0; j < 8; j++)
        v[j] = x[xoff + lane + 32*j];

    float s1 = 0.f, s2 = 0.f;
    #pragma unroll
    for (int j = 0; j < 8; j++) { s1 += v[j]; s2 += v[j]*v[j]; }
    #pragma unroll
    for (int off = 16; off > 0; off >>= 1) {
        s1 += __shfl_xor_sync(0xffffffff, s1, off);
        s2 += __shfl_xor_sync(0xffffffff, s2, off);
    }
    float mu  = s1 * (1.0f / DIM);
    float var = s2 * (1.0f / DIM) - mu * mu;
    float rs  = rsqrtf(var + 1e-5f);

    #pragma unroll
    for (int j = 0; j < 8; j++) {
        int d = lane + 32*j;
        float y = (v[j] - mu) * rs * gamma[d] + beta[d];
        __nv_bfloat16 h, l;
        split_bf16(y, h, l);
        g_a_hi[(size_t)row * DIM + d] = h;
        g_a_lo[(size_t)row * DIM + d] = l;
    }
}

// ---------------- kernel 2: QKV projection (bf16 split, cp.async pipeline) --
// C(30720x768) = A(30720x256) @ W'(256x768); CTA tile 128x128, warp 32x64.
// ONE barrier per K-step: wait0 -> sync -> issue next cp -> compute.
__global__ __launch_bounds__(256)
void qkv_mma(void)
{
    __shared__ __align__(16) __nv_bfloat16 sAh[2][128][24];   // 2-stage, 48B pitch
    __shared__ __align__(16) __nv_bfloat16 sAl[2][128][24];
    __shared__ __align__(16) __nv_bfloat16 sBh[2][128][24];
    __shared__ __align__(16) __nv_bfloat16 sBl[2][128][24];

    int tid = threadIdx.x;
    int w = tid >> 5, lane = tid & 31;
    int bx = blockIdx.x;                  // 0..5 (N tile)
    int row0 = blockIdx.y * 128;
    int col0 = bx * 128;

    int wm = w >> 1;
    int wn = w & 1;

    uint32_t aAh = smem_u32(&sAh[0][0][0]);
    uint32_t aAl = smem_u32(&sAl[0][0][0]);
    uint32_t aBh = smem_u32(&sBh[0][0][0]);
    uint32_t aBl = smem_u32(&sBl[0][0][0]);

    int lr16 = lane & 15, lk16 = (lane >> 4) * 16;
    int l7 = lane & 7, lb3 = (lane >> 3) & 1, lb4 = lane >> 4;

    float c[2][8][4];
    #pragma unroll
    for (int i = 0; i < 2; i++)
        #pragma unroll
        for (int j = 0; j < 8; j++)
            #pragma unroll
            for (int q = 0; q < 4; q++) c[i][j][q] = 0.f;

    int r = tid >> 1, hf = tid & 1;
    size_t gA = (size_t)(row0 + r) * 256 + hf * 8;
    size_t gB = (size_t)(col0 + r) * 256 + hf * 8;
    uint32_t sOfs = (uint32_t)(r * 48 + hf * 16);

    // prologue: stage 0
    CP16(aAh + sOfs, g_a_hi  + gA);
    CP16(aAl + sOfs, g_a_lo  + gA);
    CP16(aBh + sOfs, g_wt_hi + gB);
    CP16(aBl + sOfs, g_wt_lo + gB);
    CP_COMMIT();

    for (int ks = 0; ks < 16; ks++) {
        int stg = ks & 1;
        CP_WAIT0();          // data for stage stg ready (issued last iter)
        __syncthreads();     // everyone past previous stage's reads

        if (ks < 15) {       // next stage into buffer just freed
            int nst = stg ^ 1;
            uint32_t so = sOfs + (uint32_t)nst * 6144;
            size_t ko = (size_t)(ks + 1) * 16;
            CP16(aAh + so, g_a_hi  + gA + ko);
            CP16(aAl + so, g_a_lo  + gA + ko);
            CP16(aBh + so, g_wt_hi + gB + ko);
            CP16(aBl + so, g_wt_lo + gB + ko);
            CP_COMMIT();
        }

        uint32_t base = (uint32_t)stg * 6144;
        uint32_t ah[2][4], al[2][4], bb[8][2];
        #pragma unroll
        for (int mi = 0; mi < 2; mi++) {
            uint32_t ra = base + (uint32_t)((wm*32 + mi*16 + lr16) * 48 + lk16);
            LDSM4(ah[mi], aAh + ra);
            LDSM4(al[mi], aAl + ra);
        }
        // B-hi: x4-pair loads (two n-tiles per ldmatrix)
        #pragma unroll
        for (int pi = 0; pi < 4; pi++) {
            uint32_t ad = base + (uint32_t)((wn*64 + pi*16 + lb4*8 + l7) * 48
                                            + lb3*16);
            uint32_t t[4];
            LDSM4(t, aBh + ad);
            bb[2*pi][0] = t[0]; bb[2*pi][1] = t[1];
            bb[2*pi+1][0] = t[2]; bb[2*pi+1][1] = t[3];
        }
        #pragma unroll
        for (int mi = 0; mi < 2; mi++)
            #pragma unroll
            for (int ni = 0; ni < 8; ni++) {
                MMA16816(c[mi][ni], ah[mi], bb[ni]);   // Ah*Bh
                MMA16816(c[mi][ni], al[mi], bb[ni]);   // Al*Bh
            }
        // B-lo: x4-pair loads
        #pragma unroll
        for (int pi = 0; pi < 4; pi++) {
            uint32_t ad = base + (uint32_t)((wn*64 + pi*16 + lb4*8 + l7) * 48
                                            + lb3*16);
            uint32_t t[4];
            LDSM4(t, aBl + ad);
            bb[2*pi][0] = t[0]; bb[2*pi][1] = t[1];
            bb[2*pi+1][0] = t[2]; bb[2*pi+1][1] = t[3];
        }
        #pragma unroll
        for (int mi = 0; mi < 2; mi++)
            #pragma unroll
            for (int ni = 0; ni < 8; ni++)
                MMA16816(c[mi][ni], ah[mi], bb[ni]);   // Ah*Bl
    }

    // epilogue: split + store bf16 hi/lo into q/k/v
    __nv_bfloat16 *dh, *dl;
    int cbase;
    if (bx < 2)      { dh = g_q_hi; dl = g_q_lo; cbase = bx * 128; }
    else if (bx < 4) { dh = g_k_hi; dl = g_k_lo; cbase = (bx - 2) * 128; }
    else             { dh = g_v_hi; dl = g_v_lo; cbase = (bx - 4) * 128; }

    int g = lane >> 2, tg = lane & 3;
    #pragma unroll
    for (int mi = 0; mi < 2; mi++) {
        #pragma unroll
        for (int ni = 0; ni < 8; ni++) {
            int cl = cbase + wn*64 + ni*8 + tg*2;
            #pragma unroll
            for (int half = 0; half < 2; half++) {
                int rowg = row0 + wm*32 + mi*16 + g + half*8;
                uint32_t H, L;
                pack_split2(c[mi][ni][half*2+0], c[mi][ni][half*2+1], H, L);
                *(uint32_t*)(dh + (size_t)rowg * 256 + cl) = H;
                *(uint32_t*)(dl + (size_t)rowg * 256 + cl) = L;
            }
        }
    }
}

// ---------------- kernel 3: attention (flash, warp-private softmax) ---------
// grid (5 n-tiles, 8 heads, 96 batch), 128 thr = 4 warps.
// Bias kept in separate registers; S zero-init -> bias consumed AFTER the QK
// phase (load-to-use window covers DRAM latency). One barrier per chunk.
__global__ __launch_bounds__(128)
void attn_mma(const float* __restrict__ ctx)
{
    __shared__ __align__(16) __nv_bfloat16 sK[2][2][64][40];  // [stage][hi/lo]
    __shared__ __align__(16) __nv_bfloat16 sV[2][2][64][40];

    int tid = threadIdx.x;
    int lane = tid & 31, wm = tid >> 5;
    int g = lane >> 2, tg = lane & 3;
    int lr16 = lane & 15, lk16 = (lane >> 4) * 16;

    int nt = blockIdx.x, h = blockIdx.y, Bi = blockIdx.z;
    int n0 = nt * 64;
    size_t rowbase = (size_t)Bi * SEQ;

    uint32_t aK[2][2], aV[2][2];
    #pragma unroll
    for (int s = 0; s < 2; s++) {
        #pragma unroll
        for (int hl = 0; hl < 2; hl++) {
            aK[s][hl] = smem_u32(&sK[s][hl][0][0]);
            aV[s][hl] = smem_u32(&sV[s][hl][0][0]);
        }
    }

    // cp.async mapping: row = tid>>1, 32-byte half cb
    int cr = tid >> 1;
    int cb = (tid & 1) * 32;
    uint32_t so = (uint32_t)(cr * 80 + cb);
    int ce = cb >> 1;                    // element offset within row (bf16)

    // ldmatrix x4 lane addressing (K pairs / V-trans pairs)
    int l7 = lane & 7, lb3 = (lane >> 3) & 1, lb4 = lane >> 4;

    // ---- prologue: Q staged through stage-1 K region, then K/V stage 0 ----
    {
        size_t gq = (rowbase + n0 + cr) * 256 + h * 32 + ce;
        CP16(aK[1][0] + so,      g_q_hi + gq);
        CP16(aK[1][0] + so + 16, g_q_hi + gq + 8);
        CP16(aK[1][1] + so,      g_q_lo + gq);
        CP16(aK[1][1] + so + 16, g_q_lo + gq + 8);
        CP_COMMIT();
        size_t gb = (rowbase + 0 + cr) * 256 + h * 32 + ce;
        CP16(aK[0][0] + so,      g_k_hi + gb);
        CP16(aK[0][0] + so + 16, g_k_hi + gb + 8);
        CP16(aK[0][1] + so,      g_k_lo + gb);
        CP16(aK[0][1] + so + 16, g_k_lo + gb + 8);
        CP16(aV[0][0] + so,      g_v_hi + gb);
        CP16(aV[0][0] + so + 16, g_v_hi + gb + 8);
        CP16(aV[0][1] + so,      g_v_lo + gb);
        CP16(aV[0][1] + so + 16, g_v_lo + gb + 8);
        CP_COMMIT();
    }
    CP_WAIT1();              // Q group complete (stage-0 K/V may still fly)
    __syncthreads();

    uint32_t qh[2][4], ql[2][4];
    #pragma unroll
    for (int kk = 0; kk < 2; kk++) {
        uint32_t ra = (uint32_t)((wm*16 + lr16) * 80 + lk16 + kk*32);
        LDSM4(qh[kk], aK[1][0] + ra);
        LDSM4(ql[kk], aK[1][1] + ra);
    }

    const float* ctxb = ctx + (size_t)Bi * SEQ * CTXLD + (size_t)h * SEQ;

    float o[4][4];
    #pragma unroll
    for (int vi = 0; vi < 4; vi++)
        #pragma unroll
        for (int q = 0; q < 4; q++) o[vi][q] = 0.f;
    float m_lo = -1e30f, m_hi = -1e30f, l_lo = 0.f, l_hi = 0.f;

    int rl = wm*16 + g, rh = rl + 8;
    const float* bias_l = ctxb + (size_t)(n0 + rl) * CTXLD;
    const float* bias_h = ctxb + (size_t)(n0 + rh) * CTXLD;

    for (int it = 0; it < 5; it++) {
        int m0 = it * 64, stg = it & 1;

        // ---- bias loads into SEPARATE regs; consumed only after QK ----
        float b[8][4];
        #pragma unroll
        for (int ni = 0; ni < 8; ni++) {
            int colm = m0 + ni*8 + tg*2;
            float2 b0 = *(const float2*)(bias_l + colm);
            float2 b1 = *(const float2*)(bias_h + colm);
            b[ni][0] = b0.x; b[ni][1] = b0.y; b[ni][2] = b1.x; b[ni][3] = b1.y;
        }

        CP_WAIT0();          // stage stg data (issued last iteration) ready
        __syncthreads();     // all warps past previous reads; data visible

        if (it < 4) {        // issue next stage into the buffer just freed
            size_t gb = (rowbase + m0 + 64 + cr) * 256 + h * 32 + ce;
            int ns = stg ^ 1;
            CP16(aK[ns][0] + so,      g_k_hi + gb);
            CP16(aK[ns][0] + so + 16, g_k_hi + gb + 8);
            CP16(aK[ns][1] + so,      g_k_lo + gb);
            CP16(aK[ns][1] + so + 16, g_k_lo + gb + 8);
            CP16(aV[ns][0] + so,      g_v_hi + gb);
            CP16(aV[ns][0] + so + 16, g_v_hi + gb + 8);
            CP16(aV[ns][1] + so,      g_v_lo + gb);
            CP16(aV[ns][1] + so + 16, g_v_lo + gb + 8);
            CP_COMMIT();
        }

        // ---- S = Q K^T (zero-init; no dependency on bias loads) ----
        float s[8][4];
        #pragma unroll
        for (int ni = 0; ni < 8; ni++)
            #pragma unroll
            for (int q = 0; q < 4; q++) s[ni][q] = 0.f;

        #pragma unroll
        for (int kk = 0; kk < 2; kk++) {
            uint32_t bh[8][2], bl[8][2];
            #pragma unroll
            for (int pi = 0; pi < 4; pi++) {
                uint32_t ad = (uint32_t)((pi*16 + lb4*8 + l7) * 80
                                         + kk*32 + lb3*16);
                uint32_t t[4];
                LDSM4(t, aK[stg][0] + ad);
                bh[2*pi][0] = t[0]; bh[2*pi][1] = t[1];
                bh[2*pi+1][0] = t[2]; bh[2*pi+1][1] = t[3];
                LDSM4(t, aK[stg][1] + ad);
                bl[2*pi][0] = t[0]; bl[2*pi][1] = t[1];
                bl[2*pi+1][0] = t[2]; bl[2*pi+1][1] = t[3];
            }
            #pragma unroll
            for (int ni = 0; ni < 8; ni++) {
                MMA16816(s[ni], qh[kk], bh[ni]);
                MMA16816(s[ni], ql[kk], bh[ni]);
                MMA16816(s[ni], qh[kk], bl[ni]);
            }
        }

        // ---- add bias (loads have had the whole QK phase to land) ----
        #pragma unroll
        for (int ni = 0; ni < 8; ni++) {
            s[ni][0] += b[ni][0]; s[ni][1] += b[ni][1];
            s[ni][2] += b[ni][2]; s[ni][3] += b[ni][3];
        }

        // ---- warp-private online softmax (rows rl, rh) ----
        float mx0 = s[0][0], mx1 = s[0][2];
        #pragma unroll
        for (int ni = 0; ni < 8; ni++) {
            mx0 = fmaxf(mx0, fmaxf(s[ni][0], s[ni][1]));
            mx1 = fmaxf(mx1, fmaxf(s[ni][2], s[ni][3]));
        }
        mx0 = fmaxf(mx0, __shfl_xor_sync(0xffffffff, mx0, 1));
        mx0 = fmaxf(mx0, __shfl_xor_sync(0xffffffff, mx0, 2));
        mx1 = fmaxf(mx1, __shfl_xor_sync(0xffffffff, mx1, 1));
        mx1 = fmaxf(mx1, __shfl_xor_sync(0xffffffff, mx1, 2));

        float mn0 = fmaxf(m_lo, mx0);
        float mn1 = fmaxf(m_hi, mx1);
        float cor0 = __expf(m_lo - mn0);
        float cor1 = __expf(m_hi - mn1);
        m_lo = mn0; m_hi = mn1;

        float su0 = 0.f, su1 = 0.f;
        #pragma unroll
        for (int ni = 0; ni < 8; ni++) {
            s[ni][0] = __expf(s[ni][0] - mn0);
            s[ni][1] = __expf(s[ni][1] - mn0);
            s[ni][2] = __expf(s[ni][2] - mn1);
            s[ni][3] = __expf(s[ni][3] - mn1);
            su0 += s[ni][0] + s[ni][1];
            su1 += s[ni][2] + s[ni][3];
        }
        su0 += __shfl_xor_sync(0xffffffff, su0, 1);
        su0 += __shfl_xor_sync(0xffffffff, su0, 2);
        su1 += __shfl_xor_sync(0xffffffff, su1, 1);
        su1 += __shfl_xor_sync(0xffffffff, su1, 2);
        l_lo = l_lo * cor0 + su0;
        l_hi = l_hi * cor1 + su1;

        #pragma unroll
        for (int vi = 0; vi < 4; vi++) {
            o[vi][0] *= cor0; o[vi][1] *= cor0;
            o[vi][2] *= cor1; o[vi][3] *= cor1;
        }

        // ---- O += P @ V : P C-frags ARE A-frags; x4-pair trans V loads ----
        #pragma unroll
        for (int kk = 0; kk < 4; kk++) {
            uint32_t ph[4], pl[4];
            pack_split2(s[2*kk][0],   s[2*kk][1],   ph[0], pl[0]);
            pack_split2(s[2*kk][2],   s[2*kk][3],   ph[1], pl[1]);
            pack_split2(s[2*kk+1][0], s[2*kk+1][1], ph[2], pl[2]);
            pack_split2(s[2*kk+1][2], s[2*kk+1][3], ph[3], pl[3]);
            #pragma unroll
            for (int vp = 0; vp < 2; vp++) {
                uint32_t ad = (uint32_t)((kk*16 + lb3*8 + l7) * 80
                                         + (vp*2 + lb4) * 16);
                uint32_t th[4], tl[4];
                LDSM4T(th, aV[stg][0] + ad);
                LDSM4T(tl, aV[stg][1] + ad);
                uint32_t vh0[2] = {th[0], th[1]}, vh1[2] = {th[2], th[3]};
                uint32_t vl0[2] = {tl[0], tl[1]}, vl1[2] = {tl[2], tl[3]};
                MMA16816(o[vp*2],   ph, vh0);
                MMA16816(o[vp*2],   pl, vh0);
                MMA16816(o[vp*2],   ph, vl0);
                MMA16816(o[vp*2+1], ph, vh1);
                MMA16816(o[vp*2+1], pl, vh1);
                MMA16816(o[vp*2+1], ph, vl1);
            }
        }
    }

    // ---- normalize + store (no cross-warp reduction needed) ----
    float inv0 = 1.f / l_lo, inv1 = 1.f / l_hi;
    #pragma unroll
    for (int vi = 0; vi < 4; vi++) {
        int col = h*32 + vi*8 + tg*2;
        *(float2*)(g_o + (rowbase + n0 + rl) * 256 + col) =
            make_float2(o[vi][0] * inv0, o[vi][1] * inv0);
        *(float2*)(g_o + (rowbase + n0 + rh) * 256 + col) =
            make_float2(o[vi][2] * inv1, o[vi][3] * inv1);
    }
}

// ---------------- kernel 4: output projection + scatter ---------------------
__global__ __launch_bounds__(128)
void outproj_kernel(const float* __restrict__ wout, float* __restrict__ out)
{
    __shared__ __align__(16) float ws[DIM * DHEAD];
    int tid = threadIdx.x;
    for (int i = tid * 4; i < DIM * DHEAD; i += 128 * 4)
        *(float4*)&ws[i] = *(const float4*)&wout[i];
    __syncthreads();

    int row = blockIdx.x * 128 + tid;
    const float* arow = g_o + (size_t)row * DIM;

    float acc[32];
    #pragma unroll
    for (int j = 0; j < 32; j++) acc[j] = 0.f;

    for (int k4 = 0; k4 < DIM; k4 += 4) {
        float4 a = *(const float4*)(arow + k4);
        float av[4] = {a.x, a.y, a.z, a.w};
        #pragma unroll
        for (int kk = 0; kk < 4; kk++) {
            #pragma unroll
            for (int j4 = 0; j4 < 8; j4++) {
                float4 wv = *(const float4*)&ws[(k4 + kk) * DHEAD + j4 * 4];
                acc[j4*4+0] = fmaf(av[kk], wv.x, acc[j4*4+0]);
                acc[j4*4+1] = fmaf(av[kk], wv.y, acc[j4*4+1]);
                acc[j4*4+2] = fmaf(av[kk], wv.z, acc[j4*4+2]);
                acc[j4*4+3] = fmaf(av[kk], wv.w, acc[j4*4+3]);
            }
        }
    }

    int Bi = row / SEQ, n = row % SEQ;
    size_t off = x_offset(Bi, n, DHEAD);
    #pragma unroll
    for (int j4 = 0; j4 < 8; j4++)
        *(float4*)(out + off + j4 * 4) =
            make_float4(acc[j4*4], acc[j4*4+1], acc[j4*4+2], acc[j4*4+3]);
}

// ---------------- launch ----------------------------------------------------
extern "C" void kernel_launch(void* const* d_in, const int* in_sizes, int n_in,
                              void* d_out, int out_size)
{
    (void)out_size;
    // expected order: x, context, w_q, w_kv, w_out, ln_g, ln_b
    int ix = 0, ictx = 1, iwq = 2, iwkv = 3, iwout = 4, ig = 5, ib = 6;
    int g_seen = -1;
    for (int i = 0; i < n_in; i++) {
        switch (in_sizes[i]) {
            case 7864320:  ix = i;    break;
            case 78643200: ictx = i;  break;
            case 65536:    iwq = i;   break;
            case 131072:   iwkv = i;  break;
            case 8192:     iwout = i; break;
            case 256:
                if (g_seen < 0) { ig = i; g_seen = i; } else { ib = i; }
                break;
            default: break;
        }
    }

    const float* x    = (const float*)d_in[ix];
    const float* ctx  = (const float*)d_in[ictx];
    const float* wq   = (const float*)d_in[iwq];
    const float* wkv  = (const float*)d_in[iwkv];
    const float* wout = (const float*)d_in[iwout];
    const float* lng  = (const float*)d_in[ig];
    const float* lnb  = (const float*)d_in[ib];
    float* out = (float*)d_out;

    wprep_kernel<<<NQKV, 256>>>(wq, wkv);
    ln_kernel<<<NROWS/8, 256>>>(x, lng, lnb);

    dim3 g2(6, 240);
    qkv_mma<<<g2, 256>>>();

    dim3 g3(5, HEADS, BATCH);
    attn_mma<<<g3, 128>>>(ctx);

    outproj_kernel<<<240, 128>>>(wout, out);
}